// round 13
// baseline (speedup 1.0000x reference)
#include <cuda_runtime.h>
#include <cuda_fp16.h>
#include <math.h>
#include <stdint.h>

// ---------------- problem constants ----------------
#define NB   4
#define LQ   8192
#define SS   8192
#define DD   256
#define HH   8
#define HD   32
#define D2   512
#define MR   (NB*LQ)        // 32768
#define EPS_ATTN 1e-6f
#define EPS_LN   1e-5f

// ---------------- scratch (device globals) ----------------
__device__ float g_KV  [NB*HH*HD*HD];
__device__ float g_Ksum[NB*HH*HD];

__device__ __half g_ss_h [(size_t)MR*DD];
__device__ __half g_kvh  [(size_t)MR*D2];   // [row][0:256]=K, [256:512]=V (fp16)
__device__ __half g_qz_h [(size_t)MR*DD];
__device__ __half g_cat_h[(size_t)MR*D2];
__device__ __half g_h1_h [(size_t)MR*D2];

__device__ __half g_wq [DD*DD];
__device__ __half g_wkv[D2*DD];             // rows 0-255 Wk, 256-511 Wv
__device__ __half g_w1 [D2*D2];
__device__ __half g_w2 [DD*D2];
__device__ __half g_G  [NB*DD*DD];          // per-batch effective weight (KV@Wm)/SS

// ---------------- low-level helpers ----------------
__device__ __forceinline__ uint32_t smem_u32(const void* p) {
    uint32_t a;
    asm("{ .reg .u64 t; cvta.to.shared.u64 t, %1; cvt.u32.u64 %0, t; }"
        : "=r"(a) : "l"(p));
    return a;
}

__device__ __forceinline__ uint32_t sw128(uint32_t off) {
    return off ^ ((off >> 3) & 0x70);
}

#define CPASYNC16(sa, ga) \
    asm volatile("cp.async.cg.shared.global [%0], [%1], 16;" \
                 :: "r"(sa), "l"(ga) : "memory")
#define CPCOMMIT() asm volatile("cp.async.commit_group;" ::: "memory")
#define CPWAIT0()  asm volatile("cp.async.wait_group 0;" ::: "memory")
#define CPWAIT1()  asm volatile("cp.async.wait_group 1;" ::: "memory")

#define LDSM4(r, addr) \
    asm volatile("ldmatrix.sync.aligned.m8n8.x4.shared.b16 {%0,%1,%2,%3}, [%4];" \
        : "=r"((r)[0]), "=r"((r)[1]), "=r"((r)[2]), "=r"((r)[3]) : "r"(addr))

#define LDSM4T(r, addr) \
    asm volatile("ldmatrix.sync.aligned.m8n8.x4.trans.shared.b16 {%0,%1,%2,%3}, [%4];" \
        : "=r"((r)[0]), "=r"((r)[1]), "=r"((r)[2]), "=r"((r)[3]) : "r"(addr))

__device__ __forceinline__ void mma_f16(float* c, const uint32_t* a,
                                        uint32_t b0, uint32_t b1) {
    asm volatile(
        "mma.sync.aligned.m16n8k16.row.col.f32.f16.f16.f32 "
        "{%0,%1,%2,%3}, {%4,%5,%6,%7}, {%8,%9}, {%0,%1,%2,%3};"
        : "+f"(c[0]), "+f"(c[1]), "+f"(c[2]), "+f"(c[3])
        : "r"(a[0]), "r"(a[1]), "r"(a[2]), "r"(a[3]), "r"(b0), "r"(b1));
}

enum { ACT_NONE = 0, ACT_ELU1 = 1, ACT_RELU = 2, ACT_KVMIX = 3 };
enum { EPI_F32 = 0, EPI_HALF = 1, EPI_QZ = 2 };
enum { EPI_LNCAT = 0, EPI_LNRES = 1 };

// ================= persistent GEMM, 128x128 tile, fp16 =====================
#define T_BYTES   16384u
#define STG128    (2u*T_BYTES)     // 32KB/stage
#define GSMEM128  (2u*STG128)      // 64KB

template<int ACT, bool HASMASK, int EPI>
__global__ __launch_bounds__(256, 2)
void gemm128p(const __half* __restrict__ Ap, const __half* __restrict__ Bp, int lda,
              float* __restrict__ C, __half* __restrict__ Ch,
              int Nc, int K, const float* __restrict__ mask, float scale,
              const float* __restrict__ Ksum, float* __restrict__ KsumOut)
{
    extern __shared__ char smem[];
    const uint32_t sb = smem_u32(smem);
    const int tid  = threadIdx.x;
    const int lane = tid & 31;
    const int wid  = tid >> 5;
    const int wm   = wid >> 1;
    const int wn   = wid & 1;

    const int Ntl = Nc >> 7;
    const int T   = (MR >> 7) * Ntl;
    const int NCC = K >> 6;

    auto load_chunk = [&](int st, int bm, int bn, int c) {
        const int k0 = c * 64;
        const uint32_t stb = sb + st * STG128;
#pragma unroll
        for (int i = 0; i < 4; i++) {
            int ci  = tid + 256 * i;
            int row = ci >> 3;
            int c16 = ci & 7;
            uint32_t so = sw128((uint32_t)(row * 128 + c16 * 16));
            CPASYNC16(stb + so,           Ap + (size_t)(bm + row) * lda + k0 + c16 * 8);
            CPASYNC16(stb + T_BYTES + so, Bp + (size_t)(bn + row) * K   + k0 + c16 * 8);
        }
        CPCOMMIT();
    };

    const int t0 = blockIdx.x;
    if (t0 >= T) return;
    load_chunk(0, (t0 / Ntl) * 128, (t0 % Ntl) * 128, 0);

    const int a_row = wm * 32 + (lane & 15);
    const int a_kb  = (lane >> 4) * 16;
    const int b_row = wn * 64 + (lane & 7) + ((lane >> 4) << 3);
    const int b_kb  = ((lane >> 3) & 1) * 16;

    int g = 0;
    for (int t = t0; t < T; t += gridDim.x) {
        const int bm = (t / Ntl) * 128;
        const int bn = (t % Ntl) * 128;

        float acc[2][8][4];
#pragma unroll
        for (int i = 0; i < 2; i++)
#pragma unroll
            for (int j = 0; j < 8; j++)
#pragma unroll
                for (int v = 0; v < 4; v++) acc[i][j][v] = 0.f;

        for (int c = 0; c < NCC; c++) {
            if (c + 1 < NCC) {
                load_chunk((g + 1) & 1, bm, bn, c + 1);
                CPWAIT1();
            } else {
                int tn = t + gridDim.x;
                if (tn < T) {
                    load_chunk((g + 1) & 1, (tn / Ntl) * 128, (tn % Ntl) * 128, 0);
                    CPWAIT1();
                } else {
                    CPWAIT0();
                }
            }
            __syncthreads();

            const uint32_t stb = sb + (g & 1) * STG128;
#pragma unroll
            for (int ks = 0; ks < 4; ks++) {
                uint32_t ah[2][4], bh[4][4];
#pragma unroll
                for (int mt = 0; mt < 2; mt++) {
                    uint32_t ra = sw128((uint32_t)((a_row + mt * 16) * 128 + ks * 32 + a_kb));
                    LDSM4(ah[mt], stb + ra);
                }
#pragma unroll
                for (int ntp = 0; ntp < 4; ntp++) {
                    uint32_t rb = sw128((uint32_t)((b_row + ntp * 16) * 128 + ks * 32 + b_kb));
                    LDSM4(bh[ntp], stb + T_BYTES + rb);
                }
#pragma unroll
                for (int mt = 0; mt < 2; mt++)
#pragma unroll
                    for (int nt = 0; nt < 8; nt++) {
                        const int ntp = nt >> 1, o = (nt & 1) * 2;
                        mma_f16(acc[mt][nt], ah[mt], bh[ntp][o], bh[ntp][o + 1]);
                    }
            }
            g++;
            __syncthreads();
        }

        // ------------- register-direct epilogue -------------
        {
            const bool elu = (ACT == ACT_ELU1) || (ACT == ACT_KVMIX && bn < DD);
            float mk[2][2];
#pragma unroll
            for (int mt = 0; mt < 2; mt++)
#pragma unroll
                for (int rh = 0; rh < 2; rh++) {
                    int m = bm + wm * 32 + mt * 16 + (lane >> 2) + rh * 8;
                    mk[mt][rh] = (HASMASK ? mask[m] : 1.f) * scale;
                }
#pragma unroll
            for (int mt = 0; mt < 2; mt++)
#pragma unroll
                for (int nt = 0; nt < 8; nt++)
#pragma unroll
                    for (int v = 0; v < 4; v++) {
                        float xv = acc[mt][nt][v];
                        if (ACT == ACT_ELU1 || ACT == ACT_KVMIX) {
                            if (elu) xv = (xv > 0.f) ? (xv + 1.f) : expf(xv);
                        } else if (ACT == ACT_RELU) xv = fmaxf(xv, 0.f);
                        acc[mt][nt][v] = xv * mk[mt][v >> 1];
                    }

            // Ksum accumulation on K-half tiles (fp32, via free smem stage)
            if (ACT == ACT_KVMIX) {
                if (bn < DD) {
                    float* cbuf = (float*)(smem + (size_t)(((g & 1) ^ 1) * STG128));
                    if (tid < 128) cbuf[tid] = 0.f;
                    __syncthreads();
#pragma unroll
                    for (int nt = 0; nt < 8; nt++)
#pragma unroll
                        for (int j = 0; j < 2; j++) {
                            float cs = acc[0][nt][j] + acc[0][nt][2 + j]
                                     + acc[1][nt][j] + acc[1][nt][2 + j];
                            cs += __shfl_xor_sync(0xffffffffu, cs, 4);
                            cs += __shfl_xor_sync(0xffffffffu, cs, 8);
                            cs += __shfl_xor_sync(0xffffffffu, cs, 16);
                            if ((lane >> 2) == 0)
                                atomicAdd(&cbuf[wn * 64 + nt * 8 + (lane & 3) * 2 + j], cs);
                        }
                    __syncthreads();
                    if (tid < 128)
                        atomicAdd(KsumOut + (bm / LQ) * DD + bn + tid, cbuf[tid]);
                    __syncthreads();   // protect cbuf from next tile's prefetch
                }
            }

            if (EPI == EPI_QZ) {
                const int n = bm / LQ;
                float ksv[8][2];
#pragma unroll
                for (int nt = 0; nt < 8; nt++)
#pragma unroll
                    for (int j = 0; j < 2; j++)
                        ksv[nt][j] = Ksum[n * DD + bn + wn * 64 + nt * 8 + (lane & 3) * 2 + j];

                float p[2][2][2];
#pragma unroll
                for (int mt = 0; mt < 2; mt++)
#pragma unroll
                    for (int rh = 0; rh < 2; rh++)
#pragma unroll
                        for (int hg = 0; hg < 2; hg++) p[mt][rh][hg] = 0.f;
#pragma unroll
                for (int mt = 0; mt < 2; mt++)
#pragma unroll
                    for (int nt = 0; nt < 8; nt++)
#pragma unroll
                        for (int v = 0; v < 4; v++)
                            p[mt][v >> 1][nt >> 2] += acc[mt][nt][v] * ksv[nt][v & 1];

                float z[2][2][2];
#pragma unroll
                for (int mt = 0; mt < 2; mt++)
#pragma unroll
                    for (int rh = 0; rh < 2; rh++)
#pragma unroll
                        for (int hg = 0; hg < 2; hg++) {
                            float s = p[mt][rh][hg];
                            s += __shfl_xor_sync(0xffffffffu, s, 1);
                            s += __shfl_xor_sync(0xffffffffu, s, 2);
                            // SS keeps qz in fp16-normal range; 1/SS folded into G.
                            z[mt][rh][hg] = (float)SS / (s + EPS_ATTN);
                        }

#pragma unroll
                for (int mt = 0; mt < 2; mt++)
#pragma unroll
                    for (int nt = 0; nt < 8; nt++)
#pragma unroll
                        for (int rh = 0; rh < 2; rh++) {
                            int row = bm + wm * 32 + mt * 16 + (lane >> 2) + rh * 8;
                            int col = bn + wn * 64 + nt * 8 + (lane & 3) * 2;
                            float zz = z[mt][rh][nt >> 2];
                            float v0 = acc[mt][nt][rh * 2]     * zz;
                            float v1 = acc[mt][nt][rh * 2 + 1] * zz;
                            *(__half2*)(Ch + (size_t)row * DD + col) =
                                __halves2half2(__float2half_rn(v0), __float2half_rn(v1));
                        }
            } else {
#pragma unroll
                for (int mt = 0; mt < 2; mt++)
#pragma unroll
                    for (int nt = 0; nt < 8; nt++)
#pragma unroll
                        for (int rh = 0; rh < 2; rh++) {
                            int row = bm + wm * 32 + mt * 16 + (lane >> 2) + rh * 8;
                            int col = bn + wn * 64 + nt * 8 + (lane & 3) * 2;
                            float v0 = acc[mt][nt][rh * 2];
                            float v1 = acc[mt][nt][rh * 2 + 1];
                            size_t gi = (size_t)row * Nc + col;
                            if (EPI == EPI_HALF) {
                                *(__half2*)(Ch + gi) =
                                    __halves2half2(__float2half_rn(v0), __float2half_rn(v1));
                            } else {
                                *(float2*)(C + gi) = make_float2(v0, v1);
                            }
                        }
            }
        }
    }
}

// ===== persistent GEMM 64x256 tile, fused row-LN epilogue (sum-based) ======
#define A_SZ   8192u
#define B_SZ   32768u
#define STG256 (A_SZ + B_SZ)            // 40KB
#define SUMS_OFF (2u*STG256)            // 80KB
#define GSMEM256 (SUMS_OFF + 2048u)     // +2KB for row sums

template<int EPI, bool BATCHB>
__global__ __launch_bounds__(256, 2)
void gemm256p(const __half* __restrict__ Ap, const __half* __restrict__ Bp,
              int lda, int K,
              const float* __restrict__ gv_, const float* __restrict__ bv_,
              const float* __restrict__ xres,
              float* __restrict__ outf, __half* __restrict__ Ch)
{
    extern __shared__ char smem[];
    const uint32_t sb = smem_u32(smem);
    float* sums  = (float*)(smem + SUMS_OFF);   // [64][4]
    float* sumsq = sums + 256;                  // [64][4]
    const int tid  = threadIdx.x;
    const int lane = tid & 31;
    const int wid  = tid >> 5;
    const int wm   = wid >> 2;
    const int wn   = wid & 3;

    const int T   = MR / 64;   // 512
    const int NCC = K >> 6;

    float gvr[8][2], bvr[8][2];
#pragma unroll
    for (int nt = 0; nt < 8; nt++)
#pragma unroll
        for (int j = 0; j < 2; j++) {
            int col = wn * 64 + nt * 8 + (lane & 3) * 2 + j;
            gvr[nt][j] = gv_[col];
            bvr[nt][j] = bv_[col];
        }

    auto load_chunk = [&](int st, int bm, int c) {
        const int k0 = c * 64;
        const uint32_t stb = sb + st * STG256;
        const __half* Bt = BATCHB ? Bp + (size_t)(bm / LQ) * DD * DD : Bp;
#pragma unroll
        for (int i = 0; i < 10; i++) {
            int ci = tid + 256 * i;
            if (i < 2) {
                int row = ci >> 3, c16 = ci & 7;
                uint32_t so = sw128((uint32_t)(row * 128 + c16 * 16));
                CPASYNC16(stb + so, Ap + (size_t)(bm + row) * lda + k0 + c16 * 8);
            } else {
                int idx = ci - 512;
                int row = idx >> 3, c16 = idx & 7;
                uint32_t so = sw128((uint32_t)(row * 128 + c16 * 16));
                CPASYNC16(stb + A_SZ + so, Bt + (size_t)row * K + k0 + c16 * 8);
            }
        }
        CPCOMMIT();
    };

    const int t0 = blockIdx.x;
    if (t0 >= T) return;
    load_chunk(0, t0 * 64, 0);

    const int a_row = wm * 32 + (lane & 15);
    const int a_kb  = (lane >> 4) * 16;
    const int b_row = wn * 64 + (lane & 7) + ((lane >> 4) << 3);
    const int b_kb  = ((lane >> 3) & 1) * 16;

    int g = 0;
    for (int t = t0; t < T; t += gridDim.x) {
        const int bm = t * 64;

        float acc[2][8][4];
#pragma unroll
        for (int i = 0; i < 2; i++)
#pragma unroll
            for (int j = 0; j < 8; j++)
#pragma unroll
                for (int v = 0; v < 4; v++) acc[i][j][v] = 0.f;

        for (int c = 0; c < NCC; c++) {
            if (c + 1 < NCC) {
                load_chunk((g + 1) & 1, bm, c + 1);
                CPWAIT1();
            } else {
                int tn = t + gridDim.x;
                if (tn < T) {
                    load_chunk((g + 1) & 1, tn * 64, 0);
                    CPWAIT1();
                } else {
                    CPWAIT0();
                }
            }
            __syncthreads();

            const uint32_t stb = sb + (g & 1) * STG256;
#pragma unroll
            for (int ks = 0; ks < 4; ks++) {
                uint32_t ah[2][4], bh[4][4];
#pragma unroll
                for (int mt = 0; mt < 2; mt++) {
                    uint32_t ra = sw128((uint32_t)((a_row + mt * 16) * 128 + ks * 32 + a_kb));
                    LDSM4(ah[mt], stb + ra);
                }
#pragma unroll
                for (int ntp = 0; ntp < 4; ntp++) {
                    uint32_t rb = sw128((uint32_t)((b_row + ntp * 16) * 128 + ks * 32 + b_kb));
                    LDSM4(bh[ntp], stb + A_SZ + rb);
                }
#pragma unroll
                for (int mt = 0; mt < 2; mt++)
#pragma unroll
                    for (int nt = 0; nt < 8; nt++) {
                        const int ntp = nt >> 1, o = (nt & 1) * 2;
                        mma_f16(acc[mt][nt], ah[mt], bh[ntp][o], bh[ntp][o + 1]);
                    }
            }
            g++;
            __syncthreads();
        }

        // ------- LN epilogue: quad-shfl partial sums + 2KB smem reduce -------
#pragma unroll
        for (int mt = 0; mt < 2; mt++)
#pragma unroll
            for (int rh = 0; rh < 2; rh++) {
                float s = 0.f, s2 = 0.f;
#pragma unroll
                for (int nt = 0; nt < 8; nt++) {
                    float v0 = acc[mt][nt][rh * 2], v1 = acc[mt][nt][rh * 2 + 1];
                    s  += v0 + v1;
                    s2 += v0 * v0 + v1 * v1;
                }
                s  += __shfl_xor_sync(0xffffffffu, s, 1);
                s  += __shfl_xor_sync(0xffffffffu, s, 2);
                s2 += __shfl_xor_sync(0xffffffffu, s2, 1);
                s2 += __shfl_xor_sync(0xffffffffu, s2, 2);
                int rloc = wm * 32 + mt * 16 + (lane >> 2) + rh * 8;
                if ((lane & 3) == 0) {
                    sums [rloc * 4 + wn] = s;
                    sumsq[rloc * 4 + wn] = s2;
                }
            }
        __syncthreads();

#pragma unroll
        for (int mt = 0; mt < 2; mt++)
#pragma unroll
            for (int rh = 0; rh < 2; rh++) {
                int rloc = wm * 32 + mt * 16 + (lane >> 2) + rh * 8;
                float st = 0.f, s2t = 0.f;
#pragma unroll
                for (int k2 = 0; k2 < 4; k2++) {
                    st  += sums [rloc * 4 + k2];
                    s2t += sumsq[rloc * 4 + k2];
                }
                const float mu  = st * (1.f / 256.f);
                const float var = s2t * (1.f / 256.f) - mu * mu;
                const float rs  = rsqrtf(var + EPS_LN);
                const size_t gr = (size_t)(bm + rloc);
#pragma unroll
                for (int nt = 0; nt < 8; nt++) {
                    int col = wn * 64 + nt * 8 + (lane & 3) * 2;
                    float y0 = (acc[mt][nt][rh * 2]     - mu) * rs * gvr[nt][0] + bvr[nt][0];
                    float y1 = (acc[mt][nt][rh * 2 + 1] - mu) * rs * gvr[nt][1] + bvr[nt][1];
                    if (EPI == EPI_LNCAT) {
                        *(__half2*)(Ch + gr * D2 + DD + col) =
                            __halves2half2(__float2half_rn(y0), __float2half_rn(y1));
                    } else {
                        float2 xr = *(const float2*)(xres + gr * DD + col);
                        *(float2*)(outf + gr * DD + col) =
                            make_float2(xr.x + y0, xr.y + y1);
                    }
                }
            }
        __syncthreads();
    }
}

// ====== KV via tensor cores: pipelined over 8 chunks of 128 s-rows =========
// KV[n,h,d,e] = sum_s K[s,d]*V[s,e]. grid (32 nh, 8 s-splits of 1024).
__global__ __launch_bounds__(256)
void kv_tc(const __half* __restrict__ KVh)
{
    __shared__ __half Ks[2][128][40];
    __shared__ __half Vs[2][128][40];
    __shared__ float kvbuf[32][33];

    const int nh = blockIdx.x;
    const int n  = nh >> 3;
    const int h  = nh & 7;
    const int sbase = blockIdx.y * 1024;
    const int tid = threadIdx.x, lane = tid & 31, w = tid >> 5;

    const uint32_t ksb = smem_u32(&Ks[0][0][0]);
    const uint32_t vsb = smem_u32(&Vs[0][0][0]);

    auto load = [&](int st, int ch) {
        const int s0 = sbase + ch * 128;
        const uint32_t ko = ksb + st * 10240u;
        const uint32_t vo = vsb + st * 10240u;
#pragma unroll
        for (int i = 0; i < 2; i++) {
            int idx = tid + 256 * i;          // 0..511
            int row = idx >> 2, c = idx & 3;
            size_t gk = (size_t)(n * SS + s0 + row) * D2 + h * HD + c * 8;
            CPASYNC16(ko + (uint32_t)(row * 80 + c * 16), KVh + gk);
            CPASYNC16(vo + (uint32_t)(row * 80 + c * 16), KVh + gk + DD);
        }
        CPCOMMIT();
    };

    for (int i = tid; i < 32 * 33; i += 256) (&kvbuf[0][0])[i] = 0.f;

    float acc[2][4][4];
#pragma unroll
    for (int mt = 0; mt < 2; mt++)
#pragma unroll
        for (int nf = 0; nf < 4; nf++)
#pragma unroll
            for (int v = 0; v < 4; v++) acc[mt][nf][v] = 0.f;

    load(0, 0);

    const int q = lane >> 3, r = lane & 7;
    const int kr = w * 16;

    for (int ch = 0; ch < 8; ch++) {
        if (ch + 1 < 8) { load((ch + 1) & 1, ch + 1); CPWAIT1(); }
        else            { CPWAIT0(); }
        __syncthreads();

        const uint32_t ko = ksb + (uint32_t)((ch & 1) * 10240);
        const uint32_t vo = vsb + (uint32_t)((ch & 1) * 10240);

        uint32_t a[2][4], bx[4], by[4];
#pragma unroll
        for (int mt = 0; mt < 2; mt++) {
            uint32_t addr = ko + (uint32_t)((kr + (q >> 1) * 8 + r) * 80
                                            + ((q & 1) * 8 + mt * 16) * 2);
            LDSM4T(a[mt], addr);
        }
        {
            uint32_t rowb = (uint32_t)((kr + (q & 1) * 8 + r) * 80);
            LDSM4T(bx, vo + rowb + (uint32_t)(((q >> 1) * 8) * 2));
            LDSM4T(by, vo + rowb + (uint32_t)(((q >> 1) * 8 + 16) * 2));
        }
#pragma unroll
        for (int mt = 0; mt < 2; mt++) {
            mma_f16(acc[mt][0], a[mt], bx[0], bx[1]);
            mma_f16(acc[mt][1], a[mt], bx[2], bx[3]);
            mma_f16(acc[mt][2], a[mt], by[0], by[1]);
            mma_f16(acc[mt][3], a[mt], by[2], by[3]);
        }
        __syncthreads();
    }

    // reduce across warps in smem, then one global atomic pass
#pragma unroll
    for (int mt = 0; mt < 2; mt++)
#pragma unroll
        for (int nf = 0; nf < 4; nf++)
#pragma unroll
            for (int v = 0; v < 4; v++) {
                int row = mt * 16 + (lane >> 2) + (v >> 1) * 8;
                int col = nf * 8 + (lane & 3) * 2 + (v & 1);
                atomicAdd(&kvbuf[row][col], acc[mt][nf][v]);
            }
    __syncthreads();

    for (int i = tid; i < 1024; i += 256)
        atomicAdd(g_KV + (size_t)nh * 1024 + i, kvbuf[i >> 5][i & 31]);
}

// ---------------- prep (split A/B for stream overlap) ----------------
__device__ __forceinline__ void tohalf4(const float* s, __half* d, size_t si, size_t di) {
    float4 v = *(const float4*)(s + si * 4);
    __half2* dp = (__half2*)(d + di);
    dp[0] = __halves2half2(__float2half_rn(v.x), __float2half_rn(v.y));
    dp[1] = __halves2half2(__float2half_rn(v.z), __float2half_rn(v.w));
}

#define NW4  16384
#define NW1  65536
#define NW2  32768
#define NACT 2097152
#define PREPA_TOTAL (3*NW4 + NW1 + NW2 + NACT)

__global__ __launch_bounds__(256)
void prep_a_kernel(const float* __restrict__ Wq, const float* __restrict__ Wk,
                   const float* __restrict__ Wv, const float* __restrict__ W1,
                   const float* __restrict__ W2, const float* __restrict__ src)
{
    int i = blockIdx.x * 256 + threadIdx.x;
    if (i < NB * HH * HD * HD) g_KV[i] = 0.f;
    if (i < NB * HH * HD)      g_Ksum[i] = 0.f;
    if (i >= PREPA_TOTAL) return;

    int r = i;
    if (r < NW4) { tohalf4(Wq, g_wq, r, (size_t)r * 4); return; }
    r -= NW4;
    if (r < NW4) { tohalf4(Wk, g_wkv, r, (size_t)r * 4); return; }
    r -= NW4;
    if (r < NW4) { tohalf4(Wv, g_wkv, r, (size_t)(65536 + r * 4)); return; }
    r -= NW4;
    if (r < NW1) { tohalf4(W1, g_w1, r, (size_t)r * 4); return; }
    r -= NW1;
    if (r < NW2) { tohalf4(W2, g_w2, r, (size_t)r * 4); return; }
    r -= NW2;
    tohalf4(src, g_ss_h, r, (size_t)r * 4);
}

__global__ __launch_bounds__(256)
void prep_b_kernel(const float* __restrict__ x)
{
    int r = blockIdx.x * 256 + threadIdx.x;
    if (r >= NACT) return;
    int e0  = r * 4;
    int row = e0 >> 8;
    int col = e0 & 255;
    tohalf4(x, g_cat_h, r, (size_t)row * D2 + col);
}

// ------ G[n][j][h*32+d] = (1/SS) sum_e KV[n,h,d,e]*Wm[j,h*32+e] ------------
__global__ __launch_bounds__(256)
void g_kernel(const float* __restrict__ Wm)
{
    __shared__ float KVsT[HD][HD + 1];
    const int h = blockIdx.x;
    const int n = blockIdx.y;
    const int z = blockIdx.z;
    const int tid = threadIdx.x;

    for (int i = tid; i < HD * HD; i += 256) {
        int d = i >> 5, e = i & 31;
        KVsT[e][d] = g_KV[((size_t)(n * HH + h)) * HD * HD + i];
    }
    __syncthreads();

    const int d  = tid & 31;
    const int j0 = z * 32 + (tid >> 5) * 4;
    const float inv_ss = 1.f / (float)SS;
#pragma unroll
    for (int i = 0; i < 4; i++) {
        int j = j0 + i;
        const float* wrow = Wm + (size_t)j * DD + h * HD;
        float acc = 0.f;
#pragma unroll
        for (int e = 0; e < HD; e++) acc += KVsT[e][d] * wrow[e];
        ((__half*)g_G)[((size_t)n * DD + j) * DD + h * HD + d] =
            __float2half_rn(acc * inv_ss);
    }
}

// ---------------- host ----------------
static float* sym_f(const void* s) { void* p = nullptr; cudaGetSymbolAddress(&p, s); return (float*)p; }
static __half* sym_h(const void* s) { void* p = nullptr; cudaGetSymbolAddress(&p, s); return (__half*)p; }

extern "C" void kernel_launch(void* const* d_in, const int* in_sizes, int n_in,
                              void* d_out, int out_size)
{
    const float* x           = (const float*)d_in[0];
    const float* source      = (const float*)d_in[1];
    const float* x_mask      = (const float*)d_in[2];
    const float* source_mask = (const float*)d_in[3];
    const float* Wq          = (const float*)d_in[4];
    const float* Wk          = (const float*)d_in[5];
    const float* Wv          = (const float*)d_in[6];
    const float* Wm          = (const float*)d_in[7];
    const float* W1          = (const float*)d_in[8];
    const float* W2          = (const float*)d_in[9];
    const float* g1          = (const float*)d_in[10];
    const float* b1          = (const float*)d_in[11];
    const float* g2          = (const float*)d_in[12];
    const float* b2          = (const float*)d_in[13];
    float* out = (float*)d_out;

    float* pKsum = sym_f(g_Ksum);

    __half *pss = sym_h(g_ss_h), *pqz = sym_h(g_qz_h);
    __half *pct = sym_h(g_cat_h), *ph1 = sym_h(g_h1_h);
    __half *pkvh = sym_h(g_kvh);
    __half *pwq = sym_h(g_wq), *pwkv = sym_h(g_wkv);
    __half *pw1 = sym_h(g_w1), *pw2 = sym_h(g_w2), *pG = sym_h(g_G);

    cudaFuncSetAttribute(gemm128p<ACT_KVMIX, true,  EPI_HALF>, cudaFuncAttributeMaxDynamicSharedMemorySize, GSMEM128);
    cudaFuncSetAttribute(gemm128p<ACT_ELU1,  true,  EPI_QZ  >, cudaFuncAttributeMaxDynamicSharedMemorySize, GSMEM128);
    cudaFuncSetAttribute(gemm128p<ACT_RELU,  false, EPI_HALF>, cudaFuncAttributeMaxDynamicSharedMemorySize, GSMEM128);
    cudaFuncSetAttribute(gemm256p<EPI_LNCAT, true >, cudaFuncAttributeMaxDynamicSharedMemorySize, GSMEM256);
    cudaFuncSetAttribute(gemm256p<EPI_LNRES, false>, cudaFuncAttributeMaxDynamicSharedMemorySize, GSMEM256);

    int nsm = 148;
    cudaDeviceGetAttribute(&nsm, cudaDevAttrMultiProcessorCount, 0);
    const int pgrid = 2 * nsm;

    static cudaStream_t s1 = nullptr;
    static cudaEvent_t evStart, evB, evKVh, evG;
    if (s1 == nullptr) {
        cudaStreamCreateWithFlags(&s1, cudaStreamNonBlocking);
        cudaEventCreateWithFlags(&evStart, cudaEventDisableTiming);
        cudaEventCreateWithFlags(&evB,     cudaEventDisableTiming);
        cudaEventCreateWithFlags(&evKVh,   cudaEventDisableTiming);
        cudaEventCreateWithFlags(&evG,     cudaEventDisableTiming);
    }

    dim3 blk(256);

    // fork
    cudaEventRecord(evStart, 0);
    cudaStreamWaitEvent(s1, evStart, 0);

    // s1: x -> cat[:,0:256]
    prep_b_kernel<<<(NACT + 255) / 256, blk, 0, s1>>>(x);
    cudaEventRecord(evB, s1);

    // s0: weights + source converts + zero accumulators
    prep_a_kernel<<<(PREPA_TOTAL + 255) / 256, blk>>>(Wq, Wk, Wv, W1, W2, source);

    // s0: merged K|V projection -> g_kvh (fp16) + Ksum (fused, fp32)
    gemm128p<ACT_KVMIX, true, EPI_HALF><<<pgrid, blk, GSMEM128>>>(pss, pwkv, DD,
        nullptr, pkvh, D2, DD, source_mask, 1.f, nullptr, pKsum);
    cudaEventRecord(evKVh, 0);

    // s1: KV via tensor cores, then G = (KV@Wm)/SS  (overlaps qz on s0)
    cudaStreamWaitEvent(s1, evKVh, 0);
    kv_tc<<<dim3(NB * HH, 8), blk, 0, s1>>>(pkvh);
    g_kernel<<<dim3(HH, NB, 8), blk, 0, s1>>>(Wm);
    cudaEventRecord(evG, s1);

    // s0: Q projection with fused Z (Ksum already computed in KV projection)
    cudaStreamWaitEvent(0, evB, 0);
    gemm128p<ACT_ELU1, true, EPI_QZ><<<pgrid, blk, GSMEM128>>>(pct, pwq, D2,
        nullptr, pqz, DD, DD, x_mask, 1.f, pKsum, nullptr);

    // s0: msg2 = qz @ G[n].T with fused LN(g1,b1) -> cat[:,256:512] (join evG)
    cudaStreamWaitEvent(0, evG, 0);
    gemm256p<EPI_LNCAT, true><<<pgrid, blk, GSMEM256>>>(pqz, pG, DD, DD,
        g1, b1, nullptr, nullptr, pct);

    // s0: h1 = relu(cat @ W1.T)
    gemm128p<ACT_RELU, false, EPI_HALF><<<pgrid, blk, GSMEM128>>>(pct, pw1, D2,
        nullptr, ph1, D2, D2, nullptr, 1.f, nullptr, nullptr);

    // s0: out = x + LN(h1 @ W2.T)
    gemm256p<EPI_LNRES, false><<<pgrid, blk, GSMEM256>>>(ph1, pw2, D2, D2,
        g2, b2, x, out, nullptr);
}

// round 14
// speedup vs baseline: 1.0522x; 1.0522x over previous
#include <cuda_runtime.h>
#include <cuda_fp16.h>
#include <math.h>
#include <stdint.h>

// ---------------- problem constants ----------------
#define NB   4
#define LQ   8192
#define SS   8192
#define DD   256
#define HH   8
#define HD   32
#define D2   512
#define MR   (NB*LQ)        // 32768
#define EPS_ATTN 1e-6f
#define EPS_LN   1e-5f

// ---------------- scratch (device globals) ----------------
__device__ float g_KV  [NB*HH*HD*HD];
__device__ float g_Ksum[NB*HH*HD];

__device__ __half g_ss_h [(size_t)MR*DD];
__device__ __half g_kvh  [(size_t)MR*D2];   // [row][0:256]=K, [256:512]=V (fp16)
__device__ __half g_qz_h [(size_t)MR*DD];
__device__ __half g_cat_h[(size_t)MR*D2];
__device__ __half g_h1_h [(size_t)MR*D2];

__device__ __half g_wq [DD*DD];
__device__ __half g_wkv[D2*DD];             // rows 0-255 Wk, 256-511 Wv
__device__ __half g_w1 [D2*D2];
__device__ __half g_w2 [DD*D2];
__device__ __half g_G  [NB*DD*DD];          // per-batch effective weight (KV@Wm)/SS

// ---------------- low-level helpers ----------------
__device__ __forceinline__ uint32_t smem_u32(const void* p) {
    uint32_t a;
    asm("{ .reg .u64 t; cvta.to.shared.u64 t, %1; cvt.u32.u64 %0, t; }"
        : "=r"(a) : "l"(p));
    return a;
}

__device__ __forceinline__ uint32_t sw128(uint32_t off) {
    return off ^ ((off >> 3) & 0x70);
}

#define CPASYNC16(sa, ga) \
    asm volatile("cp.async.cg.shared.global [%0], [%1], 16;" \
                 :: "r"(sa), "l"(ga) : "memory")
#define CPCOMMIT() asm volatile("cp.async.commit_group;" ::: "memory")
#define CPWAIT0()  asm volatile("cp.async.wait_group 0;" ::: "memory")
#define CPWAIT1()  asm volatile("cp.async.wait_group 1;" ::: "memory")

#define LDSM4(r, addr) \
    asm volatile("ldmatrix.sync.aligned.m8n8.x4.shared.b16 {%0,%1,%2,%3}, [%4];" \
        : "=r"((r)[0]), "=r"((r)[1]), "=r"((r)[2]), "=r"((r)[3]) : "r"(addr))

#define LDSM4T(r, addr) \
    asm volatile("ldmatrix.sync.aligned.m8n8.x4.trans.shared.b16 {%0,%1,%2,%3}, [%4];" \
        : "=r"((r)[0]), "=r"((r)[1]), "=r"((r)[2]), "=r"((r)[3]) : "r"(addr))

__device__ __forceinline__ void mma_f16(float* c, const uint32_t* a,
                                        uint32_t b0, uint32_t b1) {
    asm volatile(
        "mma.sync.aligned.m16n8k16.row.col.f32.f16.f16.f32 "
        "{%0,%1,%2,%3}, {%4,%5,%6,%7}, {%8,%9}, {%0,%1,%2,%3};"
        : "+f"(c[0]), "+f"(c[1]), "+f"(c[2]), "+f"(c[3])
        : "r"(a[0]), "r"(a[1]), "r"(a[2]), "r"(a[3]), "r"(b0), "r"(b1));
}

enum { ACT_NONE = 0, ACT_ELU1 = 1, ACT_RELU = 2, ACT_KVMIX = 3 };
enum { EPI_F32 = 0, EPI_HALF = 1, EPI_QZ = 2 };
enum { EPI_LNCAT = 0, EPI_LNRES = 1 };

// ================= persistent GEMM, 128x128 tile, fp16 =====================
#define T_BYTES   16384u
#define STG128    (2u*T_BYTES)     // 32KB/stage
#define GSMEM128  (2u*STG128)      // 64KB

template<int ACT, bool HASMASK, int EPI>
__global__ __launch_bounds__(256, 2)
void gemm128p(const __half* __restrict__ Ap, const __half* __restrict__ Bp, int lda,
              float* __restrict__ C, __half* __restrict__ Ch,
              int Nc, int K, const float* __restrict__ mask, float scale,
              const float* __restrict__ Ksum)
{
    extern __shared__ char smem[];
    const uint32_t sb = smem_u32(smem);
    const int tid  = threadIdx.x;
    const int lane = tid & 31;
    const int wid  = tid >> 5;
    const int wm   = wid >> 1;
    const int wn   = wid & 1;

    const int Ntl = Nc >> 7;
    const int T   = (MR >> 7) * Ntl;
    const int NCC = K >> 6;

    auto load_chunk = [&](int st, int bm, int bn, int c) {
        const int k0 = c * 64;
        const uint32_t stb = sb + st * STG128;
#pragma unroll
        for (int i = 0; i < 4; i++) {
            int ci  = tid + 256 * i;
            int row = ci >> 3;
            int c16 = ci & 7;
            uint32_t so = sw128((uint32_t)(row * 128 + c16 * 16));
            CPASYNC16(stb + so,           Ap + (size_t)(bm + row) * lda + k0 + c16 * 8);
            CPASYNC16(stb + T_BYTES + so, Bp + (size_t)(bn + row) * K   + k0 + c16 * 8);
        }
        CPCOMMIT();
    };

    const int t0 = blockIdx.x;
    if (t0 >= T) return;
    load_chunk(0, (t0 / Ntl) * 128, (t0 % Ntl) * 128, 0);

    const int a_row = wm * 32 + (lane & 15);
    const int a_kb  = (lane >> 4) * 16;
    const int b_row = wn * 64 + (lane & 7) + ((lane >> 4) << 3);
    const int b_kb  = ((lane >> 3) & 1) * 16;

    int g = 0;
    for (int t = t0; t < T; t += gridDim.x) {
        const int bm = (t / Ntl) * 128;
        const int bn = (t % Ntl) * 128;

        float acc[2][8][4];
#pragma unroll
        for (int i = 0; i < 2; i++)
#pragma unroll
            for (int j = 0; j < 8; j++)
#pragma unroll
                for (int v = 0; v < 4; v++) acc[i][j][v] = 0.f;

        for (int c = 0; c < NCC; c++) {
            if (c + 1 < NCC) {
                load_chunk((g + 1) & 1, bm, bn, c + 1);
                CPWAIT1();
            } else {
                int tn = t + gridDim.x;
                if (tn < T) {
                    load_chunk((g + 1) & 1, (tn / Ntl) * 128, (tn % Ntl) * 128, 0);
                    CPWAIT1();
                } else {
                    CPWAIT0();
                }
            }
            __syncthreads();

            const uint32_t stb = sb + (g & 1) * STG128;
#pragma unroll
            for (int ks = 0; ks < 4; ks++) {
                uint32_t ah[2][4], bh[4][4];
#pragma unroll
                for (int mt = 0; mt < 2; mt++) {
                    uint32_t ra = sw128((uint32_t)((a_row + mt * 16) * 128 + ks * 32 + a_kb));
                    LDSM4(ah[mt], stb + ra);
                }
#pragma unroll
                for (int ntp = 0; ntp < 4; ntp++) {
                    uint32_t rb = sw128((uint32_t)((b_row + ntp * 16) * 128 + ks * 32 + b_kb));
                    LDSM4(bh[ntp], stb + T_BYTES + rb);
                }
#pragma unroll
                for (int mt = 0; mt < 2; mt++)
#pragma unroll
                    for (int nt = 0; nt < 8; nt++) {
                        const int ntp = nt >> 1, o = (nt & 1) * 2;
                        mma_f16(acc[mt][nt], ah[mt], bh[ntp][o], bh[ntp][o + 1]);
                    }
            }
            g++;
            __syncthreads();
        }

        // ------------- register-direct epilogue -------------
        {
            const bool elu = (ACT == ACT_ELU1) || (ACT == ACT_KVMIX && bn < DD);
            float mk[2][2];
#pragma unroll
            for (int mt = 0; mt < 2; mt++)
#pragma unroll
                for (int rh = 0; rh < 2; rh++) {
                    int m = bm + wm * 32 + mt * 16 + (lane >> 2) + rh * 8;
                    mk[mt][rh] = (HASMASK ? mask[m] : 1.f) * scale;
                }
#pragma unroll
            for (int mt = 0; mt < 2; mt++)
#pragma unroll
                for (int nt = 0; nt < 8; nt++)
#pragma unroll
                    for (int v = 0; v < 4; v++) {
                        float xv = acc[mt][nt][v];
                        if (ACT == ACT_ELU1 || ACT == ACT_KVMIX) {
                            if (elu) xv = (xv > 0.f) ? (xv + 1.f) : expf(xv);
                        } else if (ACT == ACT_RELU) xv = fmaxf(xv, 0.f);
                        acc[mt][nt][v] = xv * mk[mt][v >> 1];
                    }

            if (EPI == EPI_QZ) {
                const int n = bm / LQ;
                float ksv[8][2];
#pragma unroll
                for (int nt = 0; nt < 8; nt++)
#pragma unroll
                    for (int j = 0; j < 2; j++)
                        ksv[nt][j] = Ksum[n * DD + bn + wn * 64 + nt * 8 + (lane & 3) * 2 + j];

                float p[2][2][2];
#pragma unroll
                for (int mt = 0; mt < 2; mt++)
#pragma unroll
                    for (int rh = 0; rh < 2; rh++)
#pragma unroll
                        for (int hg = 0; hg < 2; hg++) p[mt][rh][hg] = 0.f;
#pragma unroll
                for (int mt = 0; mt < 2; mt++)
#pragma unroll
                    for (int nt = 0; nt < 8; nt++)
#pragma unroll
                        for (int v = 0; v < 4; v++)
                            p[mt][v >> 1][nt >> 2] += acc[mt][nt][v] * ksv[nt][v & 1];

                float z[2][2][2];
#pragma unroll
                for (int mt = 0; mt < 2; mt++)
#pragma unroll
                    for (int rh = 0; rh < 2; rh++)
#pragma unroll
                        for (int hg = 0; hg < 2; hg++) {
                            float s = p[mt][rh][hg];
                            s += __shfl_xor_sync(0xffffffffu, s, 1);
                            s += __shfl_xor_sync(0xffffffffu, s, 2);
                            // SS keeps qz in fp16-normal range; 1/SS folded into G.
                            z[mt][rh][hg] = (float)SS / (s + EPS_ATTN);
                        }

#pragma unroll
                for (int mt = 0; mt < 2; mt++)
#pragma unroll
                    for (int nt = 0; nt < 8; nt++)
#pragma unroll
                        for (int rh = 0; rh < 2; rh++) {
                            int row = bm + wm * 32 + mt * 16 + (lane >> 2) + rh * 8;
                            int col = bn + wn * 64 + nt * 8 + (lane & 3) * 2;
                            float zz = z[mt][rh][nt >> 2];
                            float v0 = acc[mt][nt][rh * 2]     * zz;
                            float v1 = acc[mt][nt][rh * 2 + 1] * zz;
                            *(__half2*)(Ch + (size_t)row * DD + col) =
                                __halves2half2(__float2half_rn(v0), __float2half_rn(v1));
                        }
            } else {
#pragma unroll
                for (int mt = 0; mt < 2; mt++)
#pragma unroll
                    for (int nt = 0; nt < 8; nt++)
#pragma unroll
                        for (int rh = 0; rh < 2; rh++) {
                            int row = bm + wm * 32 + mt * 16 + (lane >> 2) + rh * 8;
                            int col = bn + wn * 64 + nt * 8 + (lane & 3) * 2;
                            float v0 = acc[mt][nt][rh * 2];
                            float v1 = acc[mt][nt][rh * 2 + 1];
                            size_t gi = (size_t)row * Nc + col;
                            if (EPI == EPI_HALF) {
                                *(__half2*)(Ch + gi) =
                                    __halves2half2(__float2half_rn(v0), __float2half_rn(v1));
                            } else {
                                *(float2*)(C + gi) = make_float2(v0, v1);
                            }
                        }
            }
        }
    }
}

// ===== persistent GEMM 64x256 tile, fused row-LN epilogue (sum-based) ======
#define A_SZ   8192u
#define B_SZ   32768u
#define STG256 (A_SZ + B_SZ)            // 40KB
#define SUMS_OFF (2u*STG256)            // 80KB
#define GSMEM256 (SUMS_OFF + 2048u)     // +2KB for row sums

template<int EPI, bool BATCHB>
__global__ __launch_bounds__(256, 2)
void gemm256p(const __half* __restrict__ Ap, const __half* __restrict__ Bp,
              int lda, int K,
              const float* __restrict__ gv_, const float* __restrict__ bv_,
              const float* __restrict__ xres,
              float* __restrict__ outf, __half* __restrict__ Ch)
{
    extern __shared__ char smem[];
    const uint32_t sb = smem_u32(smem);
    float* sums  = (float*)(smem + SUMS_OFF);   // [64][4]
    float* sumsq = sums + 256;                  // [64][4]
    const int tid  = threadIdx.x;
    const int lane = tid & 31;
    const int wid  = tid >> 5;
    const int wm   = wid >> 2;
    const int wn   = wid & 3;

    const int T   = MR / 64;   // 512
    const int NCC = K >> 6;

    float gvr[8][2], bvr[8][2];
#pragma unroll
    for (int nt = 0; nt < 8; nt++)
#pragma unroll
        for (int j = 0; j < 2; j++) {
            int col = wn * 64 + nt * 8 + (lane & 3) * 2 + j;
            gvr[nt][j] = gv_[col];
            bvr[nt][j] = bv_[col];
        }

    auto load_chunk = [&](int st, int bm, int c) {
        const int k0 = c * 64;
        const uint32_t stb = sb + st * STG256;
        const __half* Bt = BATCHB ? Bp + (size_t)(bm / LQ) * DD * DD : Bp;
#pragma unroll
        for (int i = 0; i < 10; i++) {
            int ci = tid + 256 * i;
            if (i < 2) {
                int row = ci >> 3, c16 = ci & 7;
                uint32_t so = sw128((uint32_t)(row * 128 + c16 * 16));
                CPASYNC16(stb + so, Ap + (size_t)(bm + row) * lda + k0 + c16 * 8);
            } else {
                int idx = ci - 512;
                int row = idx >> 3, c16 = idx & 7;
                uint32_t so = sw128((uint32_t)(row * 128 + c16 * 16));
                CPASYNC16(stb + A_SZ + so, Bt + (size_t)row * K + k0 + c16 * 8);
            }
        }
        CPCOMMIT();
    };

    const int t0 = blockIdx.x;
    if (t0 >= T) return;
    load_chunk(0, t0 * 64, 0);

    const int a_row = wm * 32 + (lane & 15);
    const int a_kb  = (lane >> 4) * 16;
    const int b_row = wn * 64 + (lane & 7) + ((lane >> 4) << 3);
    const int b_kb  = ((lane >> 3) & 1) * 16;

    int g = 0;
    for (int t = t0; t < T; t += gridDim.x) {
        const int bm = t * 64;

        float acc[2][8][4];
#pragma unroll
        for (int i = 0; i < 2; i++)
#pragma unroll
            for (int j = 0; j < 8; j++)
#pragma unroll
                for (int v = 0; v < 4; v++) acc[i][j][v] = 0.f;

        for (int c = 0; c < NCC; c++) {
            if (c + 1 < NCC) {
                load_chunk((g + 1) & 1, bm, c + 1);
                CPWAIT1();
            } else {
                int tn = t + gridDim.x;
                if (tn < T) {
                    load_chunk((g + 1) & 1, tn * 64, 0);
                    CPWAIT1();
                } else {
                    CPWAIT0();
                }
            }
            __syncthreads();

            const uint32_t stb = sb + (g & 1) * STG256;
#pragma unroll
            for (int ks = 0; ks < 4; ks++) {
                uint32_t ah[2][4], bh[4][4];
#pragma unroll
                for (int mt = 0; mt < 2; mt++) {
                    uint32_t ra = sw128((uint32_t)((a_row + mt * 16) * 128 + ks * 32 + a_kb));
                    LDSM4(ah[mt], stb + ra);
                }
#pragma unroll
                for (int ntp = 0; ntp < 4; ntp++) {
                    uint32_t rb = sw128((uint32_t)((b_row + ntp * 16) * 128 + ks * 32 + b_kb));
                    LDSM4(bh[ntp], stb + A_SZ + rb);
                }
#pragma unroll
                for (int mt = 0; mt < 2; mt++)
#pragma unroll
                    for (int nt = 0; nt < 8; nt++) {
                        const int ntp = nt >> 1, o = (nt & 1) * 2;
                        mma_f16(acc[mt][nt], ah[mt], bh[ntp][o], bh[ntp][o + 1]);
                    }
            }
            g++;
            __syncthreads();
        }

        // ------- LN epilogue: quad-shfl partial sums + 2KB smem reduce -------
#pragma unroll
        for (int mt = 0; mt < 2; mt++)
#pragma unroll
            for (int rh = 0; rh < 2; rh++) {
                float s = 0.f, s2 = 0.f;
#pragma unroll
                for (int nt = 0; nt < 8; nt++) {
                    float v0 = acc[mt][nt][rh * 2], v1 = acc[mt][nt][rh * 2 + 1];
                    s  += v0 + v1;
                    s2 += v0 * v0 + v1 * v1;
                }
                s  += __shfl_xor_sync(0xffffffffu, s, 1);
                s  += __shfl_xor_sync(0xffffffffu, s, 2);
                s2 += __shfl_xor_sync(0xffffffffu, s2, 1);
                s2 += __shfl_xor_sync(0xffffffffu, s2, 2);
                int rloc = wm * 32 + mt * 16 + (lane >> 2) + rh * 8;
                if ((lane & 3) == 0) {
                    sums [rloc * 4 + wn] = s;
                    sumsq[rloc * 4 + wn] = s2;
                }
            }
        __syncthreads();

#pragma unroll
        for (int mt = 0; mt < 2; mt++)
#pragma unroll
            for (int rh = 0; rh < 2; rh++) {
                int rloc = wm * 32 + mt * 16 + (lane >> 2) + rh * 8;
                float st = 0.f, s2t = 0.f;
#pragma unroll
                for (int k2 = 0; k2 < 4; k2++) {
                    st  += sums [rloc * 4 + k2];
                    s2t += sumsq[rloc * 4 + k2];
                }
                const float mu  = st * (1.f / 256.f);
                const float var = s2t * (1.f / 256.f) - mu * mu;
                const float rs  = rsqrtf(var + EPS_LN);
                const size_t gr = (size_t)(bm + rloc);
#pragma unroll
                for (int nt = 0; nt < 8; nt++) {
                    int col = wn * 64 + nt * 8 + (lane & 3) * 2;
                    float y0 = (acc[mt][nt][rh * 2]     - mu) * rs * gvr[nt][0] + bvr[nt][0];
                    float y1 = (acc[mt][nt][rh * 2 + 1] - mu) * rs * gvr[nt][1] + bvr[nt][1];
                    if (EPI == EPI_LNCAT) {
                        *(__half2*)(Ch + gr * D2 + DD + col) =
                            __halves2half2(__float2half_rn(y0), __float2half_rn(y1));
                    } else {
                        float2 xr = *(const float2*)(xres + gr * DD + col);
                        *(float2*)(outf + gr * DD + col) =
                            make_float2(xr.x + y0, xr.y + y1);
                    }
                }
            }
        __syncthreads();
    }
}

// ====== KV via tensor cores: pipelined, grid (32 nh, 16 splits of 512) =====
// KV[n,h,d,e] = sum_s K[s,d]*V[s,e]; also Ksum[n,h,d] = sum_s K[s,d].
__global__ __launch_bounds__(256)
void kv_tc(const __half* __restrict__ KVh)
{
    __shared__ __half Ks[2][128][40];
    __shared__ __half Vs[2][128][40];
    __shared__ float kvbuf[32][33];
    __shared__ float ksbuf[8][32];

    const int nh = blockIdx.x;
    const int n  = nh >> 3;
    const int h  = nh & 7;
    const int sbase = blockIdx.y * 512;
    const int tid = threadIdx.x, lane = tid & 31, w = tid >> 5;

    const uint32_t ksb = smem_u32(&Ks[0][0][0]);
    const uint32_t vsb = smem_u32(&Vs[0][0][0]);

    auto load = [&](int st, int ch) {
        const int s0 = sbase + ch * 128;
        const uint32_t ko = ksb + st * 10240u;
        const uint32_t vo = vsb + st * 10240u;
#pragma unroll
        for (int i = 0; i < 2; i++) {
            int idx = tid + 256 * i;          // 0..511
            int row = idx >> 2, c = idx & 3;
            size_t gk = (size_t)(n * SS + s0 + row) * D2 + h * HD + c * 8;
            CPASYNC16(ko + (uint32_t)(row * 80 + c * 16), KVh + gk);
            CPASYNC16(vo + (uint32_t)(row * 80 + c * 16), KVh + gk + DD);
        }
        CPCOMMIT();
    };

    for (int i = tid; i < 32 * 33; i += 256) (&kvbuf[0][0])[i] = 0.f;

    float acc[2][4][4];
#pragma unroll
    for (int mt = 0; mt < 2; mt++)
#pragma unroll
        for (int nf = 0; nf < 4; nf++)
#pragma unroll
            for (int v = 0; v < 4; v++) acc[mt][nf][v] = 0.f;
    float ksacc = 0.f;

    load(0, 0);

    const int q = lane >> 3, r = lane & 7;
    const int kr = w * 16;
    const int ksd = tid & 31, ksr = tid >> 5;   // Ksum thread mapping

    for (int ch = 0; ch < 4; ch++) {
        if (ch + 1 < 4) { load((ch + 1) & 1, ch + 1); CPWAIT1(); }
        else            { CPWAIT0(); }
        __syncthreads();

        const uint32_t ko = ksb + (uint32_t)((ch & 1) * 10240);
        const uint32_t vo = vsb + (uint32_t)((ch & 1) * 10240);
        const int st = ch & 1;

        // Ksum partial over this chunk's 128 rows
#pragma unroll
        for (int i = 0; i < 16; i++)
            ksacc += __half2float(Ks[st][ksr + 8 * i][ksd]);

        uint32_t a[2][4], bx[4], by[4];
#pragma unroll
        for (int mt = 0; mt < 2; mt++) {
            uint32_t addr = ko + (uint32_t)((kr + (q >> 1) * 8 + r) * 80
                                            + ((q & 1) * 8 + mt * 16) * 2);
            LDSM4T(a[mt], addr);
        }
        {
            uint32_t rowb = (uint32_t)((kr + (q & 1) * 8 + r) * 80);
            LDSM4T(bx, vo + rowb + (uint32_t)(((q >> 1) * 8) * 2));
            LDSM4T(by, vo + rowb + (uint32_t)(((q >> 1) * 8 + 16) * 2));
        }
#pragma unroll
        for (int mt = 0; mt < 2; mt++) {
            mma_f16(acc[mt][0], a[mt], bx[0], bx[1]);
            mma_f16(acc[mt][1], a[mt], bx[2], bx[3]);
            mma_f16(acc[mt][2], a[mt], by[0], by[1]);
            mma_f16(acc[mt][3], a[mt], by[2], by[3]);
        }
        __syncthreads();
    }

    ksbuf[ksr][ksd] = ksacc;

    // reduce across warps in smem, then one global atomic pass
    __syncthreads();
#pragma unroll
    for (int mt = 0; mt < 2; mt++)
#pragma unroll
        for (int nf = 0; nf < 4; nf++)
#pragma unroll
            for (int v = 0; v < 4; v++) {
                int row = mt * 16 + (lane >> 2) + (v >> 1) * 8;
                int col = nf * 8 + (lane & 3) * 2 + (v & 1);
                atomicAdd(&kvbuf[row][col], acc[mt][nf][v]);
            }
    __syncthreads();

    if (tid < 32) {
        float s = 0.f;
#pragma unroll
        for (int i = 0; i < 8; i++) s += ksbuf[i][tid];
        atomicAdd(g_Ksum + nh * HD + tid, s);
    }
    for (int i = tid; i < 1024; i += 256)
        atomicAdd(g_KV + (size_t)nh * 1024 + i, kvbuf[i >> 5][i & 31]);
}

// ---------------- prep (split A/B for stream overlap) ----------------
__device__ __forceinline__ void tohalf4(const float* s, __half* d, size_t si, size_t di) {
    float4 v = *(const float4*)(s + si * 4);
    __half2* dp = (__half2*)(d + di);
    dp[0] = __halves2half2(__float2half_rn(v.x), __float2half_rn(v.y));
    dp[1] = __halves2half2(__float2half_rn(v.z), __float2half_rn(v.w));
}

#define NW4  16384
#define NW1  65536
#define NW2  32768
#define NACT 2097152
#define PREPA_TOTAL (3*NW4 + NW1 + NW2 + NACT)

__global__ __launch_bounds__(256)
void prep_a_kernel(const float* __restrict__ Wq, const float* __restrict__ Wk,
                   const float* __restrict__ Wv, const float* __restrict__ W1,
                   const float* __restrict__ W2, const float* __restrict__ src)
{
    int i = blockIdx.x * 256 + threadIdx.x;
    if (i < NB * HH * HD * HD) g_KV[i] = 0.f;
    if (i < NB * HH * HD)      g_Ksum[i] = 0.f;
    if (i >= PREPA_TOTAL) return;

    int r = i;
    if (r < NW4) { tohalf4(Wq, g_wq, r, (size_t)r * 4); return; }
    r -= NW4;
    if (r < NW4) { tohalf4(Wk, g_wkv, r, (size_t)r * 4); return; }
    r -= NW4;
    if (r < NW4) { tohalf4(Wv, g_wkv, r, (size_t)(65536 + r * 4)); return; }
    r -= NW4;
    if (r < NW1) { tohalf4(W1, g_w1, r, (size_t)r * 4); return; }
    r -= NW1;
    if (r < NW2) { tohalf4(W2, g_w2, r, (size_t)r * 4); return; }
    r -= NW2;
    tohalf4(src, g_ss_h, r, (size_t)r * 4);
}

__global__ __launch_bounds__(256)
void prep_b_kernel(const float* __restrict__ x)
{
    int r = blockIdx.x * 256 + threadIdx.x;
    if (r >= NACT) return;
    int e0  = r * 4;
    int row = e0 >> 8;
    int col = e0 & 255;
    tohalf4(x, g_cat_h, r, (size_t)row * D2 + col);
}

// ------ G[n][j][h*32+d] = (1/SS) sum_e KV[n,h,d,e]*Wm[j,h*32+e] ------------
__global__ __launch_bounds__(256)
void g_kernel(const float* __restrict__ Wm)
{
    __shared__ float KVsT[HD][HD + 1];
    const int h = blockIdx.x;
    const int n = blockIdx.y;
    const int z = blockIdx.z;
    const int tid = threadIdx.x;

    for (int i = tid; i < HD * HD; i += 256) {
        int d = i >> 5, e = i & 31;
        KVsT[e][d] = g_KV[((size_t)(n * HH + h)) * HD * HD + i];
    }
    __syncthreads();

    const int d  = tid & 31;
    const int j0 = z * 32 + (tid >> 5) * 4;
    const float inv_ss = 1.f / (float)SS;
#pragma unroll
    for (int i = 0; i < 4; i++) {
        int j = j0 + i;
        const float* wrow = Wm + (size_t)j * DD + h * HD;
        float acc = 0.f;
#pragma unroll
        for (int e = 0; e < HD; e++) acc += KVsT[e][d] * wrow[e];
        ((__half*)g_G)[((size_t)n * DD + j) * DD + h * HD + d] =
            __float2half_rn(acc * inv_ss);
    }
}

// ---------------- host ----------------
static float* sym_f(const void* s) { void* p = nullptr; cudaGetSymbolAddress(&p, s); return (float*)p; }
static __half* sym_h(const void* s) { void* p = nullptr; cudaGetSymbolAddress(&p, s); return (__half*)p; }

extern "C" void kernel_launch(void* const* d_in, const int* in_sizes, int n_in,
                              void* d_out, int out_size)
{
    const float* x           = (const float*)d_in[0];
    const float* source      = (const float*)d_in[1];
    const float* x_mask      = (const float*)d_in[2];
    const float* source_mask = (const float*)d_in[3];
    const float* Wq          = (const float*)d_in[4];
    const float* Wk          = (const float*)d_in[5];
    const float* Wv          = (const float*)d_in[6];
    const float* Wm          = (const float*)d_in[7];
    const float* W1          = (const float*)d_in[8];
    const float* W2          = (const float*)d_in[9];
    const float* g1          = (const float*)d_in[10];
    const float* b1          = (const float*)d_in[11];
    const float* g2          = (const float*)d_in[12];
    const float* b2          = (const float*)d_in[13];
    float* out = (float*)d_out;

    float* pKsum = sym_f(g_Ksum);

    __half *pss = sym_h(g_ss_h), *pqz = sym_h(g_qz_h);
    __half *pct = sym_h(g_cat_h), *ph1 = sym_h(g_h1_h);
    __half *pkvh = sym_h(g_kvh);
    __half *pwq = sym_h(g_wq), *pwkv = sym_h(g_wkv);
    __half *pw1 = sym_h(g_w1), *pw2 = sym_h(g_w2), *pG = sym_h(g_G);

    cudaFuncSetAttribute(gemm128p<ACT_KVMIX, true,  EPI_HALF>, cudaFuncAttributeMaxDynamicSharedMemorySize, GSMEM128);
    cudaFuncSetAttribute(gemm128p<ACT_ELU1,  true,  EPI_QZ  >, cudaFuncAttributeMaxDynamicSharedMemorySize, GSMEM128);
    cudaFuncSetAttribute(gemm128p<ACT_RELU,  false, EPI_HALF>, cudaFuncAttributeMaxDynamicSharedMemorySize, GSMEM128);
    cudaFuncSetAttribute(gemm256p<EPI_LNCAT, true >, cudaFuncAttributeMaxDynamicSharedMemorySize, GSMEM256);
    cudaFuncSetAttribute(gemm256p<EPI_LNRES, false>, cudaFuncAttributeMaxDynamicSharedMemorySize, GSMEM256);

    int nsm = 148;
    cudaDeviceGetAttribute(&nsm, cudaDevAttrMultiProcessorCount, 0);
    const int pgrid = 2 * nsm;

    static cudaStream_t s1 = nullptr;
    static cudaEvent_t evStart, evB, evK, evG;
    if (s1 == nullptr) {
        cudaStreamCreateWithFlags(&s1, cudaStreamNonBlocking);
        cudaEventCreateWithFlags(&evStart, cudaEventDisableTiming);
        cudaEventCreateWithFlags(&evB,     cudaEventDisableTiming);
        cudaEventCreateWithFlags(&evK,     cudaEventDisableTiming);
        cudaEventCreateWithFlags(&evG,     cudaEventDisableTiming);
    }

    dim3 blk(256);

    // fork
    cudaEventRecord(evStart, 0);
    cudaStreamWaitEvent(s1, evStart, 0);

    // s1: x -> cat[:,0:256]
    prep_b_kernel<<<(NACT + 255) / 256, blk, 0, s1>>>(x);
    cudaEventRecord(evB, s1);

    // s0: weights + source converts + zero accumulators
    prep_a_kernel<<<(PREPA_TOTAL + 255) / 256, blk>>>(Wq, Wk, Wv, W1, W2, source);

    // s0: merged K|V projection -> g_kvh (fp16), elu1 on K half only
    gemm128p<ACT_KVMIX, true, EPI_HALF><<<pgrid, blk, GSMEM128>>>(pss, pwkv, DD,
        nullptr, pkvh, D2, DD, source_mask, 1.f, nullptr);

    // s0: KV + Ksum via pipelined tensor-core kernel
    kv_tc<<<dim3(NB * HH, 16), blk>>>(pkvh);
    cudaEventRecord(evK, 0);

    // s1: G = (KV@Wm)/SS  (overlaps qz on s0)
    cudaStreamWaitEvent(s1, evK, 0);
    g_kernel<<<dim3(HH, NB, 8), blk, 0, s1>>>(Wm);
    cudaEventRecord(evG, s1);

    // s0: Q projection with fused Z
    cudaStreamWaitEvent(0, evB, 0);
    gemm128p<ACT_ELU1, true, EPI_QZ><<<pgrid, blk, GSMEM128>>>(pct, pwq, D2,
        nullptr, pqz, DD, DD, x_mask, 1.f, pKsum);

    // s0: msg2 = qz @ G[n].T with fused LN(g1,b1) -> cat[:,256:512] (join evG)
    cudaStreamWaitEvent(0, evG, 0);
    gemm256p<EPI_LNCAT, true><<<pgrid, blk, GSMEM256>>>(pqz, pG, DD, DD,
        g1, b1, nullptr, nullptr, pct);

    // s0: h1 = relu(cat @ W1.T)
    gemm128p<ACT_RELU, false, EPI_HALF><<<pgrid, blk, GSMEM128>>>(pct, pw1, D2,
        nullptr, ph1, D2, D2, nullptr, 1.f, nullptr);

    // s0: out = x + LN(h1 @ W2.T)
    gemm256p<EPI_LNRES, false><<<pgrid, blk, GSMEM256>>>(ph1, pw2, D2, D2,
        g2, b2, x, out, nullptr);
}

// round 15
// speedup vs baseline: 1.0574x; 1.0050x over previous
#include <cuda_runtime.h>
#include <cuda_fp16.h>
#include <math.h>
#include <stdint.h>

// ---------------- problem constants ----------------
#define NB   4
#define LQ   8192
#define SS   8192
#define DD   256
#define HH   8
#define HD   32
#define D2   512
#define MR   (NB*LQ)        // 32768
#define EPS_ATTN 1e-6f
#define EPS_LN   1e-5f

// ---------------- scratch (device globals) ----------------
__device__ float g_KV  [NB*HH*HD*HD];
__device__ float g_Ksum[NB*HH*HD];

__device__ __half g_ss_h [(size_t)MR*DD];
__device__ __half g_kvh  [(size_t)MR*D2];   // [row][0:256]=K, [256:512]=V (fp16)
__device__ __half g_qz_h [(size_t)MR*DD];
__device__ __half g_cat_h[(size_t)MR*D2];
__device__ __half g_h1_h [(size_t)MR*D2];

__device__ __half g_wq [DD*DD];
__device__ __half g_wkv[D2*DD];             // rows 0-255 Wk, 256-511 Wv
__device__ __half g_w1 [D2*D2];
__device__ __half g_w2 [DD*D2];
__device__ __half g_G  [NB*DD*DD];          // per-batch effective weight (KV@Wm)/SS

// ---------------- low-level helpers ----------------
__device__ __forceinline__ uint32_t smem_u32(const void* p) {
    uint32_t a;
    asm("{ .reg .u64 t; cvta.to.shared.u64 t, %1; cvt.u32.u64 %0, t; }"
        : "=r"(a) : "l"(p));
    return a;
}

__device__ __forceinline__ uint32_t sw128(uint32_t off) {
    return off ^ ((off >> 3) & 0x70);
}

#define CPASYNC16(sa, ga) \
    asm volatile("cp.async.cg.shared.global [%0], [%1], 16;" \
                 :: "r"(sa), "l"(ga) : "memory")
#define CPCOMMIT() asm volatile("cp.async.commit_group;" ::: "memory")
#define CPWAIT0()  asm volatile("cp.async.wait_group 0;" ::: "memory")
#define CPWAIT1()  asm volatile("cp.async.wait_group 1;" ::: "memory")
#define CPWAIT2()  asm volatile("cp.async.wait_group 2;" ::: "memory")

#define LDSM4(r, addr) \
    asm volatile("ldmatrix.sync.aligned.m8n8.x4.shared.b16 {%0,%1,%2,%3}, [%4];" \
        : "=r"((r)[0]), "=r"((r)[1]), "=r"((r)[2]), "=r"((r)[3]) : "r"(addr))

#define LDSM4T(r, addr) \
    asm volatile("ldmatrix.sync.aligned.m8n8.x4.trans.shared.b16 {%0,%1,%2,%3}, [%4];" \
        : "=r"((r)[0]), "=r"((r)[1]), "=r"((r)[2]), "=r"((r)[3]) : "r"(addr))

__device__ __forceinline__ void mma_f16(float* c, const uint32_t* a,
                                        uint32_t b0, uint32_t b1) {
    asm volatile(
        "mma.sync.aligned.m16n8k16.row.col.f32.f16.f16.f32 "
        "{%0,%1,%2,%3}, {%4,%5,%6,%7}, {%8,%9}, {%0,%1,%2,%3};"
        : "+f"(c[0]), "+f"(c[1]), "+f"(c[2]), "+f"(c[3])
        : "r"(a[0]), "r"(a[1]), "r"(a[2]), "r"(a[3]), "r"(b0), "r"(b1));
}

enum { ACT_NONE = 0, ACT_ELU1 = 1, ACT_RELU = 2, ACT_KVMIX = 3 };
enum { EPI_F32 = 0, EPI_HALF = 1, EPI_QZ = 2 };
enum { EPI_LNCAT = 0, EPI_LNRES = 1 };

// ================= persistent GEMM, 128x128 tile, fp16 =====================
#define T_BYTES   16384u
#define STG128    (2u*T_BYTES)     // 32KB/stage
#define GSMEM128  (2u*STG128)      // 64KB

template<int ACT, bool HASMASK, int EPI>
__global__ __launch_bounds__(256, 2)
void gemm128p(const __half* __restrict__ Ap, const __half* __restrict__ Bp, int lda,
              float* __restrict__ C, __half* __restrict__ Ch,
              int Nc, int K, const float* __restrict__ mask, float scale,
              const float* __restrict__ Ksum)
{
    extern __shared__ char smem[];
    const uint32_t sb = smem_u32(smem);
    const int tid  = threadIdx.x;
    const int lane = tid & 31;
    const int wid  = tid >> 5;
    const int wm   = wid >> 1;
    const int wn   = wid & 1;

    const int Ntl = Nc >> 7;
    const int T   = (MR >> 7) * Ntl;
    const int NCC = K >> 6;

    auto load_chunk = [&](int st, int bm, int bn, int c) {
        const int k0 = c * 64;
        const uint32_t stb = sb + st * STG128;
#pragma unroll
        for (int i = 0; i < 4; i++) {
            int ci  = tid + 256 * i;
            int row = ci >> 3;
            int c16 = ci & 7;
            uint32_t so = sw128((uint32_t)(row * 128 + c16 * 16));
            CPASYNC16(stb + so,           Ap + (size_t)(bm + row) * lda + k0 + c16 * 8);
            CPASYNC16(stb + T_BYTES + so, Bp + (size_t)(bn + row) * K   + k0 + c16 * 8);
        }
        CPCOMMIT();
    };

    const int t0 = blockIdx.x;
    if (t0 >= T) return;
    load_chunk(0, (t0 / Ntl) * 128, (t0 % Ntl) * 128, 0);

    const int a_row = wm * 32 + (lane & 15);
    const int a_kb  = (lane >> 4) * 16;
    const int b_row = wn * 64 + (lane & 7) + ((lane >> 4) << 3);
    const int b_kb  = ((lane >> 3) & 1) * 16;

    int g = 0;
    for (int t = t0; t < T; t += gridDim.x) {
        const int bm = (t / Ntl) * 128;
        const int bn = (t % Ntl) * 128;

        float acc[2][8][4];
#pragma unroll
        for (int i = 0; i < 2; i++)
#pragma unroll
            for (int j = 0; j < 8; j++)
#pragma unroll
                for (int v = 0; v < 4; v++) acc[i][j][v] = 0.f;

        for (int c = 0; c < NCC; c++) {
            if (c + 1 < NCC) {
                load_chunk((g + 1) & 1, bm, bn, c + 1);
                CPWAIT1();
            } else {
                int tn = t + gridDim.x;
                if (tn < T) {
                    load_chunk((g + 1) & 1, (tn / Ntl) * 128, (tn % Ntl) * 128, 0);
                    CPWAIT1();
                } else {
                    CPWAIT0();
                }
            }
            __syncthreads();

            const uint32_t stb = sb + (g & 1) * STG128;
#pragma unroll
            for (int ks = 0; ks < 4; ks++) {
                uint32_t ah[2][4], bh[4][4];
#pragma unroll
                for (int mt = 0; mt < 2; mt++) {
                    uint32_t ra = sw128((uint32_t)((a_row + mt * 16) * 128 + ks * 32 + a_kb));
                    LDSM4(ah[mt], stb + ra);
                }
#pragma unroll
                for (int ntp = 0; ntp < 4; ntp++) {
                    uint32_t rb = sw128((uint32_t)((b_row + ntp * 16) * 128 + ks * 32 + b_kb));
                    LDSM4(bh[ntp], stb + T_BYTES + rb);
                }
#pragma unroll
                for (int mt = 0; mt < 2; mt++)
#pragma unroll
                    for (int nt = 0; nt < 8; nt++) {
                        const int ntp = nt >> 1, o = (nt & 1) * 2;
                        mma_f16(acc[mt][nt], ah[mt], bh[ntp][o], bh[ntp][o + 1]);
                    }
            }
            g++;
            __syncthreads();
        }

        // ------------- register-direct epilogue -------------
        {
            const bool elu = (ACT == ACT_ELU1) || (ACT == ACT_KVMIX && bn < DD);
            float mk[2][2];
#pragma unroll
            for (int mt = 0; mt < 2; mt++)
#pragma unroll
                for (int rh = 0; rh < 2; rh++) {
                    int m = bm + wm * 32 + mt * 16 + (lane >> 2) + rh * 8;
                    mk[mt][rh] = (HASMASK ? mask[m] : 1.f) * scale;
                }
#pragma unroll
            for (int mt = 0; mt < 2; mt++)
#pragma unroll
                for (int nt = 0; nt < 8; nt++)
#pragma unroll
                    for (int v = 0; v < 4; v++) {
                        float xv = acc[mt][nt][v];
                        if (ACT == ACT_ELU1 || ACT == ACT_KVMIX) {
                            if (elu) xv = (xv > 0.f) ? (xv + 1.f) : expf(xv);
                        } else if (ACT == ACT_RELU) xv = fmaxf(xv, 0.f);
                        acc[mt][nt][v] = xv * mk[mt][v >> 1];
                    }

            if (EPI == EPI_QZ) {
                const int n = bm / LQ;
                float ksv[8][2];
#pragma unroll
                for (int nt = 0; nt < 8; nt++)
#pragma unroll
                    for (int j = 0; j < 2; j++)
                        ksv[nt][j] = Ksum[n * DD + bn + wn * 64 + nt * 8 + (lane & 3) * 2 + j];

                float p[2][2][2];
#pragma unroll
                for (int mt = 0; mt < 2; mt++)
#pragma unroll
                    for (int rh = 0; rh < 2; rh++)
#pragma unroll
                        for (int hg = 0; hg < 2; hg++) p[mt][rh][hg] = 0.f;
#pragma unroll
                for (int mt = 0; mt < 2; mt++)
#pragma unroll
                    for (int nt = 0; nt < 8; nt++)
#pragma unroll
                        for (int v = 0; v < 4; v++)
                            p[mt][v >> 1][nt >> 2] += acc[mt][nt][v] * ksv[nt][v & 1];

                float z[2][2][2];
#pragma unroll
                for (int mt = 0; mt < 2; mt++)
#pragma unroll
                    for (int rh = 0; rh < 2; rh++)
#pragma unroll
                        for (int hg = 0; hg < 2; hg++) {
                            float s = p[mt][rh][hg];
                            s += __shfl_xor_sync(0xffffffffu, s, 1);
                            s += __shfl_xor_sync(0xffffffffu, s, 2);
                            // SS keeps qz in fp16-normal range; 1/SS folded into G.
                            z[mt][rh][hg] = (float)SS / (s + EPS_ATTN);
                        }

#pragma unroll
                for (int mt = 0; mt < 2; mt++)
#pragma unroll
                    for (int nt = 0; nt < 8; nt++)
#pragma unroll
                        for (int rh = 0; rh < 2; rh++) {
                            int row = bm + wm * 32 + mt * 16 + (lane >> 2) + rh * 8;
                            int col = bn + wn * 64 + nt * 8 + (lane & 3) * 2;
                            float zz = z[mt][rh][nt >> 2];
                            float v0 = acc[mt][nt][rh * 2]     * zz;
                            float v1 = acc[mt][nt][rh * 2 + 1] * zz;
                            *(__half2*)(Ch + (size_t)row * DD + col) =
                                __halves2half2(__float2half_rn(v0), __float2half_rn(v1));
                        }
            } else {
#pragma unroll
                for (int mt = 0; mt < 2; mt++)
#pragma unroll
                    for (int nt = 0; nt < 8; nt++)
#pragma unroll
                        for (int rh = 0; rh < 2; rh++) {
                            int row = bm + wm * 32 + mt * 16 + (lane >> 2) + rh * 8;
                            int col = bn + wn * 64 + nt * 8 + (lane & 3) * 2;
                            float v0 = acc[mt][nt][rh * 2];
                            float v1 = acc[mt][nt][rh * 2 + 1];
                            size_t gi = (size_t)row * Nc + col;
                            if (EPI == EPI_HALF) {
                                *(__half2*)(Ch + gi) =
                                    __halves2half2(__float2half_rn(v0), __float2half_rn(v1));
                            } else {
                                *(float2*)(C + gi) = make_float2(v0, v1);
                            }
                        }
            }
        }
    }
}

// ===== persistent GEMM 64x256 tile, fused row-LN epilogue (sum-based) ======
#define A_SZ   8192u
#define B_SZ   32768u
#define STG256 (A_SZ + B_SZ)            // 40KB
#define SUMS_OFF (2u*STG256)            // 80KB
#define GSMEM256 (SUMS_OFF + 2048u)     // +2KB for row sums

template<int EPI, bool BATCHB>
__global__ __launch_bounds__(256, 2)
void gemm256p(const __half* __restrict__ Ap, const __half* __restrict__ Bp,
              int lda, int K,
              const float* __restrict__ gv_, const float* __restrict__ bv_,
              const float* __restrict__ xres,
              float* __restrict__ outf, __half* __restrict__ Ch)
{
    extern __shared__ char smem[];
    const uint32_t sb = smem_u32(smem);
    float* sums  = (float*)(smem + SUMS_OFF);   // [64][4]
    float* sumsq = sums + 256;                  // [64][4]
    const int tid  = threadIdx.x;
    const int lane = tid & 31;
    const int wid  = tid >> 5;
    const int wm   = wid >> 2;
    const int wn   = wid & 3;

    const int T   = MR / 64;   // 512
    const int NCC = K >> 6;

    float gvr[8][2], bvr[8][2];
#pragma unroll
    for (int nt = 0; nt < 8; nt++)
#pragma unroll
        for (int j = 0; j < 2; j++) {
            int col = wn * 64 + nt * 8 + (lane & 3) * 2 + j;
            gvr[nt][j] = gv_[col];
            bvr[nt][j] = bv_[col];
        }

    auto load_chunk = [&](int st, int bm, int c) {
        const int k0 = c * 64;
        const uint32_t stb = sb + st * STG256;
        const __half* Bt = BATCHB ? Bp + (size_t)(bm / LQ) * DD * DD : Bp;
#pragma unroll
        for (int i = 0; i < 10; i++) {
            int ci = tid + 256 * i;
            if (i < 2) {
                int row = ci >> 3, c16 = ci & 7;
                uint32_t so = sw128((uint32_t)(row * 128 + c16 * 16));
                CPASYNC16(stb + so, Ap + (size_t)(bm + row) * lda + k0 + c16 * 8);
            } else {
                int idx = ci - 512;
                int row = idx >> 3, c16 = idx & 7;
                uint32_t so = sw128((uint32_t)(row * 128 + c16 * 16));
                CPASYNC16(stb + A_SZ + so, Bt + (size_t)row * K + k0 + c16 * 8);
            }
        }
        CPCOMMIT();
    };

    const int t0 = blockIdx.x;
    if (t0 >= T) return;
    load_chunk(0, t0 * 64, 0);

    const int a_row = wm * 32 + (lane & 15);
    const int a_kb  = (lane >> 4) * 16;
    const int b_row = wn * 64 + (lane & 7) + ((lane >> 4) << 3);
    const int b_kb  = ((lane >> 3) & 1) * 16;

    int g = 0;
    for (int t = t0; t < T; t += gridDim.x) {
        const int bm = t * 64;

        float acc[2][8][4];
#pragma unroll
        for (int i = 0; i < 2; i++)
#pragma unroll
            for (int j = 0; j < 8; j++)
#pragma unroll
                for (int v = 0; v < 4; v++) acc[i][j][v] = 0.f;

        for (int c = 0; c < NCC; c++) {
            if (c + 1 < NCC) {
                load_chunk((g + 1) & 1, bm, c + 1);
                CPWAIT1();
            } else {
                int tn = t + gridDim.x;
                if (tn < T) {
                    load_chunk((g + 1) & 1, tn * 64, 0);
                    CPWAIT1();
                } else {
                    CPWAIT0();
                }
            }
            __syncthreads();

            const uint32_t stb = sb + (g & 1) * STG256;
#pragma unroll
            for (int ks = 0; ks < 4; ks++) {
                uint32_t ah[2][4], bh[4][4];
#pragma unroll
                for (int mt = 0; mt < 2; mt++) {
                    uint32_t ra = sw128((uint32_t)((a_row + mt * 16) * 128 + ks * 32 + a_kb));
                    LDSM4(ah[mt], stb + ra);
                }
#pragma unroll
                for (int ntp = 0; ntp < 4; ntp++) {
                    uint32_t rb = sw128((uint32_t)((b_row + ntp * 16) * 128 + ks * 32 + b_kb));
                    LDSM4(bh[ntp], stb + A_SZ + rb);
                }
#pragma unroll
                for (int mt = 0; mt < 2; mt++)
#pragma unroll
                    for (int nt = 0; nt < 8; nt++) {
                        const int ntp = nt >> 1, o = (nt & 1) * 2;
                        mma_f16(acc[mt][nt], ah[mt], bh[ntp][o], bh[ntp][o + 1]);
                    }
            }
            g++;
            __syncthreads();
        }

        // ------- LN epilogue: quad-shfl partial sums + 2KB smem reduce -------
#pragma unroll
        for (int mt = 0; mt < 2; mt++)
#pragma unroll
            for (int rh = 0; rh < 2; rh++) {
                float s = 0.f, s2 = 0.f;
#pragma unroll
                for (int nt = 0; nt < 8; nt++) {
                    float v0 = acc[mt][nt][rh * 2], v1 = acc[mt][nt][rh * 2 + 1];
                    s  += v0 + v1;
                    s2 += v0 * v0 + v1 * v1;
                }
                s  += __shfl_xor_sync(0xffffffffu, s, 1);
                s  += __shfl_xor_sync(0xffffffffu, s, 2);
                s2 += __shfl_xor_sync(0xffffffffu, s2, 1);
                s2 += __shfl_xor_sync(0xffffffffu, s2, 2);
                int rloc = wm * 32 + mt * 16 + (lane >> 2) + rh * 8;
                if ((lane & 3) == 0) {
                    sums [rloc * 4 + wn] = s;
                    sumsq[rloc * 4 + wn] = s2;
                }
            }
        __syncthreads();

#pragma unroll
        for (int mt = 0; mt < 2; mt++)
#pragma unroll
            for (int rh = 0; rh < 2; rh++) {
                int rloc = wm * 32 + mt * 16 + (lane >> 2) + rh * 8;
                float st = 0.f, s2t = 0.f;
#pragma unroll
                for (int k2 = 0; k2 < 4; k2++) {
                    st  += sums [rloc * 4 + k2];
                    s2t += sumsq[rloc * 4 + k2];
                }
                const float mu  = st * (1.f / 256.f);
                const float var = s2t * (1.f / 256.f) - mu * mu;
                const float rs  = rsqrtf(var + EPS_LN);
                const size_t gr = (size_t)(bm + rloc);
#pragma unroll
                for (int nt = 0; nt < 8; nt++) {
                    int col = wn * 64 + nt * 8 + (lane & 3) * 2;
                    float y0 = (acc[mt][nt][rh * 2]     - mu) * rs * gvr[nt][0] + bvr[nt][0];
                    float y1 = (acc[mt][nt][rh * 2 + 1] - mu) * rs * gvr[nt][1] + bvr[nt][1];
                    if (EPI == EPI_LNCAT) {
                        *(__half2*)(Ch + gr * D2 + DD + col) =
                            __halves2half2(__float2half_rn(y0), __float2half_rn(y1));
                    } else {
                        float2 xr = *(const float2*)(xres + gr * DD + col);
                        *(float2*)(outf + gr * DD + col) =
                            make_float2(xr.x + y0, xr.y + y1);
                    }
                }
            }
        __syncthreads();
    }
}

// ====== KV via tensor cores: 4-stage pipeline, grid (32 nh, 8 splits) ======
// KV[n,h,d,e] = sum_s K[s,d]*V[s,e]; Ksum[n,h,d] = sum_s K[s,d].
// Each block: 1024 s-rows as 8 chunks of 128; dynamic smem 4 stages x 20KB.
#define KVSTG 20480u   // K(10240) + V(10240) per stage
#define KVSMEM (4u*KVSTG)

__global__ __launch_bounds__(256)
void kv_tc(const __half* __restrict__ KVh)
{
    extern __shared__ char dsm[];
    __shared__ float kvbuf[32][33];
    __shared__ float ksbuf[8][32];

    const uint32_t base = smem_u32(dsm);
    const int nh = blockIdx.x;
    const int n  = nh >> 3;
    const int h  = nh & 7;
    const int sbase = blockIdx.y * 1024;
    const int tid = threadIdx.x, lane = tid & 31, w = tid >> 5;

    auto load = [&](int ch) {
        const int s0 = sbase + ch * 128;
        const uint32_t ko = base + (uint32_t)((ch & 3) * KVSTG);
        const uint32_t vo = ko + 10240u;
#pragma unroll
        for (int i = 0; i < 2; i++) {
            int idx = tid + 256 * i;          // 0..511
            int row = idx >> 2, c = idx & 3;
            size_t gk = (size_t)(n * SS + s0 + row) * D2 + h * HD + c * 8;
            CPASYNC16(ko + (uint32_t)(row * 80 + c * 16), KVh + gk);
            CPASYNC16(vo + (uint32_t)(row * 80 + c * 16), KVh + gk + DD);
        }
        CPCOMMIT();
    };

    for (int i = tid; i < 32 * 33; i += 256) (&kvbuf[0][0])[i] = 0.f;

    float acc[2][4][4];
#pragma unroll
    for (int mt = 0; mt < 2; mt++)
#pragma unroll
        for (int nf = 0; nf < 4; nf++)
#pragma unroll
            for (int v = 0; v < 4; v++) acc[mt][nf][v] = 0.f;
    float ksacc = 0.f;

    load(0); load(1); load(2);

    const int q = lane >> 3, r = lane & 7;
    const int kr = w * 16;
    const int ksd = tid & 31, ksr = tid >> 5;

    for (int ch = 0; ch < 8; ch++) {
        if (ch <= 4)      { CPWAIT2(); }
        else if (ch == 5) { CPWAIT2(); }
        else if (ch == 6) { CPWAIT1(); }
        else              { CPWAIT0(); }
        __syncthreads();

        const uint32_t ko = base + (uint32_t)((ch & 3) * KVSTG);
        const uint32_t vo = ko + 10240u;
        const __half* ksm = (const __half*)(dsm + (ch & 3) * KVSTG);

        // Ksum partial over this chunk's 128 rows
#pragma unroll
        for (int i = 0; i < 16; i++)
            ksacc += __half2float(ksm[(ksr + 8 * i) * 40 + ksd]);

        uint32_t a[2][4], bx[4], by[4];
#pragma unroll
        for (int mt = 0; mt < 2; mt++) {
            uint32_t addr = ko + (uint32_t)((kr + (q >> 1) * 8 + r) * 80
                                            + ((q & 1) * 8 + mt * 16) * 2);
            LDSM4T(a[mt], addr);
        }
        {
            uint32_t rowb = (uint32_t)((kr + (q & 1) * 8 + r) * 80);
            LDSM4T(bx, vo + rowb + (uint32_t)(((q >> 1) * 8) * 2));
            LDSM4T(by, vo + rowb + (uint32_t)(((q >> 1) * 8 + 16) * 2));
        }
#pragma unroll
        for (int mt = 0; mt < 2; mt++) {
            mma_f16(acc[mt][0], a[mt], bx[0], bx[1]);
            mma_f16(acc[mt][1], a[mt], bx[2], bx[3]);
            mma_f16(acc[mt][2], a[mt], by[0], by[1]);
            mma_f16(acc[mt][3], a[mt], by[2], by[3]);
        }
        __syncthreads();
        if (ch + 3 < 8) load(ch + 3);
    }

    ksbuf[ksr][ksd] = ksacc;
    __syncthreads();

#pragma unroll
    for (int mt = 0; mt < 2; mt++)
#pragma unroll
        for (int nf = 0; nf < 4; nf++)
#pragma unroll
            for (int v = 0; v < 4; v++) {
                int row = mt * 16 + (lane >> 2) + (v >> 1) * 8;
                int col = nf * 8 + (lane & 3) * 2 + (v & 1);
                atomicAdd(&kvbuf[row][col], acc[mt][nf][v]);
            }
    __syncthreads();

    if (tid < 32) {
        float s = 0.f;
#pragma unroll
        for (int i = 0; i < 8; i++) s += ksbuf[i][tid];
        atomicAdd(g_Ksum + nh * HD + tid, s);
    }
    for (int i = tid; i < 1024; i += 256)
        atomicAdd(g_KV + (size_t)nh * 1024 + i, kvbuf[i >> 5][i & 31]);
}

// ---------------- prep (split A/B for stream overlap) ----------------
__device__ __forceinline__ void tohalf4(const float* s, __half* d, size_t si, size_t di) {
    float4 v = *(const float4*)(s + si * 4);
    __half2* dp = (__half2*)(d + di);
    dp[0] = __halves2half2(__float2half_rn(v.x), __float2half_rn(v.y));
    dp[1] = __halves2half2(__float2half_rn(v.z), __float2half_rn(v.w));
}

#define NW4  16384
#define NW1  65536
#define NW2  32768
#define NACT 2097152
#define PREPA_TOTAL (3*NW4 + NW1 + NW2 + NACT)

__global__ __launch_bounds__(256)
void prep_a_kernel(const float* __restrict__ Wq, const float* __restrict__ Wk,
                   const float* __restrict__ Wv, const float* __restrict__ W1,
                   const float* __restrict__ W2, const float* __restrict__ src)
{
    int i = blockIdx.x * 256 + threadIdx.x;
    if (i < NB * HH * HD * HD) g_KV[i] = 0.f;
    if (i < NB * HH * HD)      g_Ksum[i] = 0.f;
    if (i >= PREPA_TOTAL) return;

    int r = i;
    if (r < NW4) { tohalf4(Wq, g_wq, r, (size_t)r * 4); return; }
    r -= NW4;
    if (r < NW4) { tohalf4(Wk, g_wkv, r, (size_t)r * 4); return; }
    r -= NW4;
    if (r < NW4) { tohalf4(Wv, g_wkv, r, (size_t)(65536 + r * 4)); return; }
    r -= NW4;
    if (r < NW1) { tohalf4(W1, g_w1, r, (size_t)r * 4); return; }
    r -= NW1;
    if (r < NW2) { tohalf4(W2, g_w2, r, (size_t)r * 4); return; }
    r -= NW2;
    tohalf4(src, g_ss_h, r, (size_t)r * 4);
}

__global__ __launch_bounds__(256)
void prep_b_kernel(const float* __restrict__ x)
{
    int r = blockIdx.x * 256 + threadIdx.x;
    if (r >= NACT) return;
    int e0  = r * 4;
    int row = e0 >> 8;
    int col = e0 & 255;
    tohalf4(x, g_cat_h, r, (size_t)row * D2 + col);
}

// ------ G[n][j][h*32+d] = (1/SS) sum_e KV[n,h,d,e]*Wm[j,h*32+e] ------------
__global__ __launch_bounds__(256)
void g_kernel(const float* __restrict__ Wm)
{
    __shared__ float KVsT[HD][HD + 1];
    const int h = blockIdx.x;
    const int n = blockIdx.y;
    const int z = blockIdx.z;
    const int tid = threadIdx.x;

    for (int i = tid; i < HD * HD; i += 256) {
        int d = i >> 5, e = i & 31;
        KVsT[e][d] = g_KV[((size_t)(n * HH + h)) * HD * HD + i];
    }
    __syncthreads();

    const int d  = tid & 31;
    const int j0 = z * 32 + (tid >> 5) * 4;
    const float inv_ss = 1.f / (float)SS;
#pragma unroll
    for (int i = 0; i < 4; i++) {
        int j = j0 + i;
        const float* wrow = Wm + (size_t)j * DD + h * HD;
        float acc = 0.f;
#pragma unroll
        for (int e = 0; e < HD; e++) acc += KVsT[e][d] * wrow[e];
        ((__half*)g_G)[((size_t)n * DD + j) * DD + h * HD + d] =
            __float2half_rn(acc * inv_ss);
    }
}

// ---------------- host ----------------
static float* sym_f(const void* s) { void* p = nullptr; cudaGetSymbolAddress(&p, s); return (float*)p; }
static __half* sym_h(const void* s) { void* p = nullptr; cudaGetSymbolAddress(&p, s); return (__half*)p; }

extern "C" void kernel_launch(void* const* d_in, const int* in_sizes, int n_in,
                              void* d_out, int out_size)
{
    const float* x           = (const float*)d_in[0];
    const float* source      = (const float*)d_in[1];
    const float* x_mask      = (const float*)d_in[2];
    const float* source_mask = (const float*)d_in[3];
    const float* Wq          = (const float*)d_in[4];
    const float* Wk          = (const float*)d_in[5];
    const float* Wv          = (const float*)d_in[6];
    const float* Wm          = (const float*)d_in[7];
    const float* W1          = (const float*)d_in[8];
    const float* W2          = (const float*)d_in[9];
    const float* g1          = (const float*)d_in[10];
    const float* b1          = (const float*)d_in[11];
    const float* g2          = (const float*)d_in[12];
    const float* b2          = (const float*)d_in[13];
    float* out = (float*)d_out;

    float* pKsum = sym_f(g_Ksum);

    __half *pss = sym_h(g_ss_h), *pqz = sym_h(g_qz_h);
    __half *pct = sym_h(g_cat_h), *ph1 = sym_h(g_h1_h);
    __half *pkvh = sym_h(g_kvh);
    __half *pwq = sym_h(g_wq), *pwkv = sym_h(g_wkv);
    __half *pw1 = sym_h(g_w1), *pw2 = sym_h(g_w2), *pG = sym_h(g_G);

    cudaFuncSetAttribute(gemm128p<ACT_KVMIX, true,  EPI_HALF>, cudaFuncAttributeMaxDynamicSharedMemorySize, GSMEM128);
    cudaFuncSetAttribute(gemm128p<ACT_ELU1,  true,  EPI_QZ  >, cudaFuncAttributeMaxDynamicSharedMemorySize, GSMEM128);
    cudaFuncSetAttribute(gemm128p<ACT_RELU,  false, EPI_HALF>, cudaFuncAttributeMaxDynamicSharedMemorySize, GSMEM128);
    cudaFuncSetAttribute(gemm256p<EPI_LNCAT, true >, cudaFuncAttributeMaxDynamicSharedMemorySize, GSMEM256);
    cudaFuncSetAttribute(gemm256p<EPI_LNRES, false>, cudaFuncAttributeMaxDynamicSharedMemorySize, GSMEM256);
    cudaFuncSetAttribute(kv_tc, cudaFuncAttributeMaxDynamicSharedMemorySize, KVSMEM);

    int nsm = 148;
    cudaDeviceGetAttribute(&nsm, cudaDevAttrMultiProcessorCount, 0);
    const int pgrid = 2 * nsm;

    static cudaStream_t s1 = nullptr;
    static cudaEvent_t evStart, evB, evK, evG;
    if (s1 == nullptr) {
        cudaStreamCreateWithFlags(&s1, cudaStreamNonBlocking);
        cudaEventCreateWithFlags(&evStart, cudaEventDisableTiming);
        cudaEventCreateWithFlags(&evB,     cudaEventDisableTiming);
        cudaEventCreateWithFlags(&evK,     cudaEventDisableTiming);
        cudaEventCreateWithFlags(&evG,     cudaEventDisableTiming);
    }

    dim3 blk(256);

    // fork
    cudaEventRecord(evStart, 0);
    cudaStreamWaitEvent(s1, evStart, 0);

    // s1: x -> cat[:,0:256]
    prep_b_kernel<<<(NACT + 255) / 256, blk, 0, s1>>>(x);
    cudaEventRecord(evB, s1);

    // s0: weights + source converts + zero accumulators
    prep_a_kernel<<<(PREPA_TOTAL + 255) / 256, blk>>>(Wq, Wk, Wv, W1, W2, source);

    // s0: merged K|V projection -> g_kvh (fp16), elu1 on K half only
    gemm128p<ACT_KVMIX, true, EPI_HALF><<<pgrid, blk, GSMEM128>>>(pss, pwkv, DD,
        nullptr, pkvh, D2, DD, source_mask, 1.f, nullptr);

    // s0: KV + Ksum via 4-stage pipelined tensor-core kernel
    kv_tc<<<dim3(NB * HH, 8), blk, KVSMEM>>>(pkvh);
    cudaEventRecord(evK, 0);

    // s1: G = (KV@Wm)/SS  (overlaps qz on s0)
    cudaStreamWaitEvent(s1, evK, 0);
    g_kernel<<<dim3(HH, NB, 8), blk, 0, s1>>>(Wm);
    cudaEventRecord(evG, s1);

    // s0: Q projection with fused Z
    cudaStreamWaitEvent(0, evB, 0);
    gemm128p<ACT_ELU1, true, EPI_QZ><<<pgrid, blk, GSMEM128>>>(pct, pwq, D2,
        nullptr, pqz, DD, DD, x_mask, 1.f, pKsum);

    // s0: msg2 = qz @ G[n].T with fused LN(g1,b1) -> cat[:,256:512] (join evG)
    cudaStreamWaitEvent(0, evG, 0);
    gemm256p<EPI_LNCAT, true><<<pgrid, blk, GSMEM256>>>(pqz, pG, DD, DD,
        g1, b1, nullptr, nullptr, pct);

    // s0: h1 = relu(cat @ W1.T)
    gemm128p<ACT_RELU, false, EPI_HALF><<<pgrid, blk, GSMEM128>>>(pct, pw1, D2,
        nullptr, ph1, D2, D2, nullptr, 1.f, nullptr);

    // s0: out = x + LN(h1 @ W2.T)
    gemm256p<EPI_LNRES, false><<<pgrid, blk, GSMEM256>>>(ph1, pw2, D2, D2,
        g2, b2, x, out, nullptr);
}

// round 16
// speedup vs baseline: 1.0623x; 1.0047x over previous
#include <cuda_runtime.h>
#include <cuda_fp16.h>
#include <math.h>
#include <stdint.h>

// ---------------- problem constants ----------------
#define NB   4
#define LQ   8192
#define SS   8192
#define DD   256
#define HH   8
#define HD   32
#define D2   512
#define MR   (NB*LQ)        // 32768
#define EPS_ATTN 1e-6f
#define EPS_LN   1e-5f

// ---------------- scratch (device globals) ----------------
__device__ float g_KV  [NB*HH*HD*HD];
__device__ float g_Ksum[NB*HH*HD];

__device__ __half g_ss_h [(size_t)MR*DD];
__device__ __half g_kvh  [(size_t)MR*D2];   // [row][0:256]=K, [256:512]=V (fp16)
__device__ __half g_qz_h [(size_t)MR*DD];
__device__ __half g_cat_h[(size_t)MR*D2];
__device__ __half g_h1_h [(size_t)MR*D2];

__device__ __half g_wq [DD*DD];
__device__ __half g_wkv[D2*DD];             // rows 0-255 Wk, 256-511 Wv
__device__ __half g_w1 [D2*D2];
__device__ __half g_w2 [DD*D2];
__device__ __half g_G  [NB*DD*DD];          // per-batch effective weight (KV@Wm)/SS

// ---------------- low-level helpers ----------------
__device__ __forceinline__ uint32_t smem_u32(const void* p) {
    uint32_t a;
    asm("{ .reg .u64 t; cvta.to.shared.u64 t, %1; cvt.u32.u64 %0, t; }"
        : "=r"(a) : "l"(p));
    return a;
}

__device__ __forceinline__ uint32_t sw128(uint32_t off) {
    return off ^ ((off >> 3) & 0x70);
}

#define CPASYNC16(sa, ga) \
    asm volatile("cp.async.cg.shared.global [%0], [%1], 16;" \
                 :: "r"(sa), "l"(ga) : "memory")
#define CPCOMMIT() asm volatile("cp.async.commit_group;" ::: "memory")
#define CPWAIT0()  asm volatile("cp.async.wait_group 0;" ::: "memory")
#define CPWAIT1()  asm volatile("cp.async.wait_group 1;" ::: "memory")

#define LDSM4(r, addr) \
    asm volatile("ldmatrix.sync.aligned.m8n8.x4.shared.b16 {%0,%1,%2,%3}, [%4];" \
        : "=r"((r)[0]), "=r"((r)[1]), "=r"((r)[2]), "=r"((r)[3]) : "r"(addr))

#define LDSM4T(r, addr) \
    asm volatile("ldmatrix.sync.aligned.m8n8.x4.trans.shared.b16 {%0,%1,%2,%3}, [%4];" \
        : "=r"((r)[0]), "=r"((r)[1]), "=r"((r)[2]), "=r"((r)[3]) : "r"(addr))

__device__ __forceinline__ void mma_f16(float* c, const uint32_t* a,
                                        uint32_t b0, uint32_t b1) {
    asm volatile(
        "mma.sync.aligned.m16n8k16.row.col.f32.f16.f16.f32 "
        "{%0,%1,%2,%3}, {%4,%5,%6,%7}, {%8,%9}, {%0,%1,%2,%3};"
        : "+f"(c[0]), "+f"(c[1]), "+f"(c[2]), "+f"(c[3])
        : "r"(a[0]), "r"(a[1]), "r"(a[2]), "r"(a[3]), "r"(b0), "r"(b1));
}

enum { ACT_NONE = 0, ACT_ELU1 = 1, ACT_RELU = 2, ACT_KVMIX = 3 };
enum { EPI_F32 = 0, EPI_HALF = 1, EPI_QZ = 2 };
enum { EPI_LNCAT = 0, EPI_LNRES = 1 };

// ================= persistent GEMM, 128x128 tile, fp16 =====================
#define T_BYTES   16384u
#define STG128    (2u*T_BYTES)     // 32KB/stage
#define GSMEM128  (2u*STG128)      // 64KB

template<int ACT, bool HASMASK, int EPI>
__global__ __launch_bounds__(256, 2)
void gemm128p(const __half* __restrict__ Ap, const __half* __restrict__ Bp, int lda,
              float* __restrict__ C, __half* __restrict__ Ch,
              int Nc, int K, const float* __restrict__ mask, float scale,
              const float* __restrict__ Ksum)
{
    extern __shared__ char smem[];
    const uint32_t sb = smem_u32(smem);
    const int tid  = threadIdx.x;
    const int lane = tid & 31;
    const int wid  = tid >> 5;
    const int wm   = wid >> 1;
    const int wn   = wid & 1;

    const int Ntl = Nc >> 7;
    const int T   = (MR >> 7) * Ntl;
    const int NCC = K >> 6;

    auto load_chunk = [&](int st, int bm, int bn, int c) {
        const int k0 = c * 64;
        const uint32_t stb = sb + st * STG128;
#pragma unroll
        for (int i = 0; i < 4; i++) {
            int ci  = tid + 256 * i;
            int row = ci >> 3;
            int c16 = ci & 7;
            uint32_t so = sw128((uint32_t)(row * 128 + c16 * 16));
            CPASYNC16(stb + so,           Ap + (size_t)(bm + row) * lda + k0 + c16 * 8);
            CPASYNC16(stb + T_BYTES + so, Bp + (size_t)(bn + row) * K   + k0 + c16 * 8);
        }
        CPCOMMIT();
    };

    const int t0 = blockIdx.x;
    if (t0 >= T) return;
    load_chunk(0, (t0 / Ntl) * 128, (t0 % Ntl) * 128, 0);

    const int a_row = wm * 32 + (lane & 15);
    const int a_kb  = (lane >> 4) * 16;
    const int b_row = wn * 64 + (lane & 7) + ((lane >> 4) << 3);
    const int b_kb  = ((lane >> 3) & 1) * 16;

    int g = 0;
    for (int t = t0; t < T; t += gridDim.x) {
        const int bm = (t / Ntl) * 128;
        const int bn = (t % Ntl) * 128;

        float acc[2][8][4];
#pragma unroll
        for (int i = 0; i < 2; i++)
#pragma unroll
            for (int j = 0; j < 8; j++)
#pragma unroll
                for (int v = 0; v < 4; v++) acc[i][j][v] = 0.f;

        for (int c = 0; c < NCC; c++) {
            if (c + 1 < NCC) {
                load_chunk((g + 1) & 1, bm, bn, c + 1);
                CPWAIT1();
            } else {
                int tn = t + gridDim.x;
                if (tn < T) {
                    load_chunk((g + 1) & 1, (tn / Ntl) * 128, (tn % Ntl) * 128, 0);
                    CPWAIT1();
                } else {
                    CPWAIT0();
                }
            }
            __syncthreads();

            const uint32_t stb = sb + (g & 1) * STG128;
#pragma unroll
            for (int ks = 0; ks < 4; ks++) {
                uint32_t ah[2][4], bh[4][4];
#pragma unroll
                for (int mt = 0; mt < 2; mt++) {
                    uint32_t ra = sw128((uint32_t)((a_row + mt * 16) * 128 + ks * 32 + a_kb));
                    LDSM4(ah[mt], stb + ra);
                }
#pragma unroll
                for (int ntp = 0; ntp < 4; ntp++) {
                    uint32_t rb = sw128((uint32_t)((b_row + ntp * 16) * 128 + ks * 32 + b_kb));
                    LDSM4(bh[ntp], stb + T_BYTES + rb);
                }
#pragma unroll
                for (int mt = 0; mt < 2; mt++)
#pragma unroll
                    for (int nt = 0; nt < 8; nt++) {
                        const int ntp = nt >> 1, o = (nt & 1) * 2;
                        mma_f16(acc[mt][nt], ah[mt], bh[ntp][o], bh[ntp][o + 1]);
                    }
            }
            g++;
            __syncthreads();
        }

        // ------------- register-direct epilogue -------------
        {
            const bool elu = (ACT == ACT_ELU1) || (ACT == ACT_KVMIX && bn < DD);
            float mk[2][2];
#pragma unroll
            for (int mt = 0; mt < 2; mt++)
#pragma unroll
                for (int rh = 0; rh < 2; rh++) {
                    int m = bm + wm * 32 + mt * 16 + (lane >> 2) + rh * 8;
                    mk[mt][rh] = (HASMASK ? mask[m] : 1.f) * scale;
                }
#pragma unroll
            for (int mt = 0; mt < 2; mt++)
#pragma unroll
                for (int nt = 0; nt < 8; nt++)
#pragma unroll
                    for (int v = 0; v < 4; v++) {
                        float xv = acc[mt][nt][v];
                        if (ACT == ACT_ELU1 || ACT == ACT_KVMIX) {
                            if (elu) xv = (xv > 0.f) ? (xv + 1.f) : expf(xv);
                        } else if (ACT == ACT_RELU) xv = fmaxf(xv, 0.f);
                        acc[mt][nt][v] = xv * mk[mt][v >> 1];
                    }

            if (EPI == EPI_QZ) {
                const int n = bm / LQ;
                float ksv[8][2];
#pragma unroll
                for (int nt = 0; nt < 8; nt++)
#pragma unroll
                    for (int j = 0; j < 2; j++)
                        ksv[nt][j] = Ksum[n * DD + bn + wn * 64 + nt * 8 + (lane & 3) * 2 + j];

                float p[2][2][2];
#pragma unroll
                for (int mt = 0; mt < 2; mt++)
#pragma unroll
                    for (int rh = 0; rh < 2; rh++)
#pragma unroll
                        for (int hg = 0; hg < 2; hg++) p[mt][rh][hg] = 0.f;
#pragma unroll
                for (int mt = 0; mt < 2; mt++)
#pragma unroll
                    for (int nt = 0; nt < 8; nt++)
#pragma unroll
                        for (int v = 0; v < 4; v++)
                            p[mt][v >> 1][nt >> 2] += acc[mt][nt][v] * ksv[nt][v & 1];

                float z[2][2][2];
#pragma unroll
                for (int mt = 0; mt < 2; mt++)
#pragma unroll
                    for (int rh = 0; rh < 2; rh++)
#pragma unroll
                        for (int hg = 0; hg < 2; hg++) {
                            float s = p[mt][rh][hg];
                            s += __shfl_xor_sync(0xffffffffu, s, 1);
                            s += __shfl_xor_sync(0xffffffffu, s, 2);
                            // SS keeps qz in fp16-normal range; 1/SS folded into G.
                            z[mt][rh][hg] = (float)SS / (s + EPS_ATTN);
                        }

#pragma unroll
                for (int mt = 0; mt < 2; mt++)
#pragma unroll
                    for (int nt = 0; nt < 8; nt++)
#pragma unroll
                        for (int rh = 0; rh < 2; rh++) {
                            int row = bm + wm * 32 + mt * 16 + (lane >> 2) + rh * 8;
                            int col = bn + wn * 64 + nt * 8 + (lane & 3) * 2;
                            float zz = z[mt][rh][nt >> 2];
                            float v0 = acc[mt][nt][rh * 2]     * zz;
                            float v1 = acc[mt][nt][rh * 2 + 1] * zz;
                            *(__half2*)(Ch + (size_t)row * DD + col) =
                                __halves2half2(__float2half_rn(v0), __float2half_rn(v1));
                        }
            } else {
#pragma unroll
                for (int mt = 0; mt < 2; mt++)
#pragma unroll
                    for (int nt = 0; nt < 8; nt++)
#pragma unroll
                        for (int rh = 0; rh < 2; rh++) {
                            int row = bm + wm * 32 + mt * 16 + (lane >> 2) + rh * 8;
                            int col = bn + wn * 64 + nt * 8 + (lane & 3) * 2;
                            float v0 = acc[mt][nt][rh * 2];
                            float v1 = acc[mt][nt][rh * 2 + 1];
                            size_t gi = (size_t)row * Nc + col;
                            if (EPI == EPI_HALF) {
                                *(__half2*)(Ch + gi) =
                                    __halves2half2(__float2half_rn(v0), __float2half_rn(v1));
                            } else {
                                *(float2*)(C + gi) = make_float2(v0, v1);
                            }
                        }
            }
        }
    }
}

// ===== persistent GEMM 64x256 tile, fused row-LN epilogue (sum-based) ======
#define A_SZ   8192u
#define B_SZ   32768u
#define STG256 (A_SZ + B_SZ)            // 40KB
#define SUMS_OFF (2u*STG256)            // 80KB
#define GSMEM256 (SUMS_OFF + 2048u)     // +2KB for row sums

template<int EPI, bool BATCHB>
__global__ __launch_bounds__(256, 2)
void gemm256p(const __half* __restrict__ Ap, const __half* __restrict__ Bp,
              int lda, int K,
              const float* __restrict__ gv_, const float* __restrict__ bv_,
              const float* __restrict__ xres,
              float* __restrict__ outf, __half* __restrict__ Ch)
{
    extern __shared__ char smem[];
    const uint32_t sb = smem_u32(smem);
    float* sums  = (float*)(smem + SUMS_OFF);   // [64][4]
    float* sumsq = sums + 256;                  // [64][4]
    const int tid  = threadIdx.x;
    const int lane = tid & 31;
    const int wid  = tid >> 5;
    const int wm   = wid >> 2;
    const int wn   = wid & 3;

    const int T   = MR / 64;   // 512
    const int NCC = K >> 6;

    float gvr[8][2], bvr[8][2];
#pragma unroll
    for (int nt = 0; nt < 8; nt++)
#pragma unroll
        for (int j = 0; j < 2; j++) {
            int col = wn * 64 + nt * 8 + (lane & 3) * 2 + j;
            gvr[nt][j] = gv_[col];
            bvr[nt][j] = bv_[col];
        }

    auto load_chunk = [&](int st, int bm, int c) {
        const int k0 = c * 64;
        const uint32_t stb = sb + st * STG256;
        const __half* Bt = BATCHB ? Bp + (size_t)(bm / LQ) * DD * DD : Bp;
#pragma unroll
        for (int i = 0; i < 10; i++) {
            int ci = tid + 256 * i;
            if (i < 2) {
                int row = ci >> 3, c16 = ci & 7;
                uint32_t so = sw128((uint32_t)(row * 128 + c16 * 16));
                CPASYNC16(stb + so, Ap + (size_t)(bm + row) * lda + k0 + c16 * 8);
            } else {
                int idx = ci - 512;
                int row = idx >> 3, c16 = idx & 7;
                uint32_t so = sw128((uint32_t)(row * 128 + c16 * 16));
                CPASYNC16(stb + A_SZ + so, Bt + (size_t)row * K + k0 + c16 * 8);
            }
        }
        CPCOMMIT();
    };

    const int t0 = blockIdx.x;
    if (t0 >= T) return;
    load_chunk(0, t0 * 64, 0);

    const int a_row = wm * 32 + (lane & 15);
    const int a_kb  = (lane >> 4) * 16;
    const int b_row = wn * 64 + (lane & 7) + ((lane >> 4) << 3);
    const int b_kb  = ((lane >> 3) & 1) * 16;

    int g = 0;
    for (int t = t0; t < T; t += gridDim.x) {
        const int bm = t * 64;

        float acc[2][8][4];
#pragma unroll
        for (int i = 0; i < 2; i++)
#pragma unroll
            for (int j = 0; j < 8; j++)
#pragma unroll
                for (int v = 0; v < 4; v++) acc[i][j][v] = 0.f;

        for (int c = 0; c < NCC; c++) {
            if (c + 1 < NCC) {
                load_chunk((g + 1) & 1, bm, c + 1);
                CPWAIT1();
            } else {
                int tn = t + gridDim.x;
                if (tn < T) {
                    load_chunk((g + 1) & 1, tn * 64, 0);
                    CPWAIT1();
                } else {
                    CPWAIT0();
                }
            }
            __syncthreads();

            const uint32_t stb = sb + (g & 1) * STG256;
#pragma unroll
            for (int ks = 0; ks < 4; ks++) {
                uint32_t ah[2][4], bh[4][4];
#pragma unroll
                for (int mt = 0; mt < 2; mt++) {
                    uint32_t ra = sw128((uint32_t)((a_row + mt * 16) * 128 + ks * 32 + a_kb));
                    LDSM4(ah[mt], stb + ra);
                }
#pragma unroll
                for (int ntp = 0; ntp < 4; ntp++) {
                    uint32_t rb = sw128((uint32_t)((b_row + ntp * 16) * 128 + ks * 32 + b_kb));
                    LDSM4(bh[ntp], stb + A_SZ + rb);
                }
#pragma unroll
                for (int mt = 0; mt < 2; mt++)
#pragma unroll
                    for (int nt = 0; nt < 8; nt++) {
                        const int ntp = nt >> 1, o = (nt & 1) * 2;
                        mma_f16(acc[mt][nt], ah[mt], bh[ntp][o], bh[ntp][o + 1]);
                    }
            }
            g++;
            __syncthreads();
        }

        // ------- LN epilogue: quad-shfl partial sums + 2KB smem reduce -------
#pragma unroll
        for (int mt = 0; mt < 2; mt++)
#pragma unroll
            for (int rh = 0; rh < 2; rh++) {
                float s = 0.f, s2 = 0.f;
#pragma unroll
                for (int nt = 0; nt < 8; nt++) {
                    float v0 = acc[mt][nt][rh * 2], v1 = acc[mt][nt][rh * 2 + 1];
                    s  += v0 + v1;
                    s2 += v0 * v0 + v1 * v1;
                }
                s  += __shfl_xor_sync(0xffffffffu, s, 1);
                s  += __shfl_xor_sync(0xffffffffu, s, 2);
                s2 += __shfl_xor_sync(0xffffffffu, s2, 1);
                s2 += __shfl_xor_sync(0xffffffffu, s2, 2);
                int rloc = wm * 32 + mt * 16 + (lane >> 2) + rh * 8;
                if ((lane & 3) == 0) {
                    sums [rloc * 4 + wn] = s;
                    sumsq[rloc * 4 + wn] = s2;
                }
            }
        __syncthreads();

#pragma unroll
        for (int mt = 0; mt < 2; mt++)
#pragma unroll
            for (int rh = 0; rh < 2; rh++) {
                int rloc = wm * 32 + mt * 16 + (lane >> 2) + rh * 8;
                float st = 0.f, s2t = 0.f;
#pragma unroll
                for (int k2 = 0; k2 < 4; k2++) {
                    st  += sums [rloc * 4 + k2];
                    s2t += sumsq[rloc * 4 + k2];
                }
                const float mu  = st * (1.f / 256.f);
                const float var = s2t * (1.f / 256.f) - mu * mu;
                const float rs  = rsqrtf(var + EPS_LN);
                const size_t gr = (size_t)(bm + rloc);
#pragma unroll
                for (int nt = 0; nt < 8; nt++) {
                    int col = wn * 64 + nt * 8 + (lane & 3) * 2;
                    float y0 = (acc[mt][nt][rh * 2]     - mu) * rs * gvr[nt][0] + bvr[nt][0];
                    float y1 = (acc[mt][nt][rh * 2 + 1] - mu) * rs * gvr[nt][1] + bvr[nt][1];
                    if (EPI == EPI_LNCAT) {
                        *(__half2*)(Ch + gr * D2 + DD + col) =
                            __halves2half2(__float2half_rn(y0), __float2half_rn(y1));
                    } else {
                        float2 xr = *(const float2*)(xres + gr * DD + col);
                        *(float2*)(outf + gr * DD + col) =
                            make_float2(xr.x + y0, xr.y + y1);
                    }
                }
            }
        __syncthreads();
    }
}

// ====== KV via tensor cores: 2-stage pipeline (R13-calibrated optimum) =====
// KV[n,h,d,e] = sum_s K[s,d]*V[s,e]; Ksum[n,h,d] = sum_s K[s,d].
// grid (32 nh, 8 splits of 1024); 8 chunks of 128 rows, double-buffered.
__global__ __launch_bounds__(256, 2)
void kv_tc(const __half* __restrict__ KVh)
{
    __shared__ __half Ks[2][128][40];
    __shared__ __half Vs[2][128][40];
    __shared__ float kvbuf[32][33];
    __shared__ float ksbuf[8][32];

    const int nh = blockIdx.x;
    const int n  = nh >> 3;
    const int h  = nh & 7;
    const int sbase = blockIdx.y * 1024;
    const int tid = threadIdx.x, lane = tid & 31, w = tid >> 5;

    const uint32_t ksb = smem_u32(&Ks[0][0][0]);
    const uint32_t vsb = smem_u32(&Vs[0][0][0]);

    auto load = [&](int st, int ch) {
        const int s0 = sbase + ch * 128;
        const uint32_t ko = ksb + st * 10240u;
        const uint32_t vo = vsb + st * 10240u;
#pragma unroll
        for (int i = 0; i < 2; i++) {
            int idx = tid + 256 * i;          // 0..511
            int row = idx >> 2, c = idx & 3;
            size_t gk = (size_t)(n * SS + s0 + row) * D2 + h * HD + c * 8;
            CPASYNC16(ko + (uint32_t)(row * 80 + c * 16), KVh + gk);
            CPASYNC16(vo + (uint32_t)(row * 80 + c * 16), KVh + gk + DD);
        }
        CPCOMMIT();
    };

    for (int i = tid; i < 32 * 33; i += 256) (&kvbuf[0][0])[i] = 0.f;

    float acc[2][4][4];
#pragma unroll
    for (int mt = 0; mt < 2; mt++)
#pragma unroll
        for (int nf = 0; nf < 4; nf++)
#pragma unroll
            for (int v = 0; v < 4; v++) acc[mt][nf][v] = 0.f;
    float ksacc = 0.f;

    load(0, 0);

    const int q = lane >> 3, r = lane & 7;
    const int kr = w * 16;
    const int ksd = tid & 31, ksr = tid >> 5;

    for (int ch = 0; ch < 8; ch++) {
        if (ch + 1 < 8) { load((ch + 1) & 1, ch + 1); CPWAIT1(); }
        else            { CPWAIT0(); }
        __syncthreads();

        const int st = ch & 1;
        const uint32_t ko = ksb + (uint32_t)(st * 10240);
        const uint32_t vo = vsb + (uint32_t)(st * 10240);

        // Ksum partial over this chunk's 128 rows
#pragma unroll
        for (int i = 0; i < 16; i++)
            ksacc += __half2float(Ks[st][ksr + 8 * i][ksd]);

        uint32_t a[2][4], bx[4], by[4];
#pragma unroll
        for (int mt = 0; mt < 2; mt++) {
            uint32_t addr = ko + (uint32_t)((kr + (q >> 1) * 8 + r) * 80
                                            + ((q & 1) * 8 + mt * 16) * 2);
            LDSM4T(a[mt], addr);
        }
        {
            uint32_t rowb = (uint32_t)((kr + (q & 1) * 8 + r) * 80);
            LDSM4T(bx, vo + rowb + (uint32_t)(((q >> 1) * 8) * 2));
            LDSM4T(by, vo + rowb + (uint32_t)(((q >> 1) * 8 + 16) * 2));
        }
#pragma unroll
        for (int mt = 0; mt < 2; mt++) {
            mma_f16(acc[mt][0], a[mt], bx[0], bx[1]);
            mma_f16(acc[mt][1], a[mt], bx[2], bx[3]);
            mma_f16(acc[mt][2], a[mt], by[0], by[1]);
            mma_f16(acc[mt][3], a[mt], by[2], by[3]);
        }
        __syncthreads();
    }

    ksbuf[ksr][ksd] = ksacc;
    __syncthreads();

#pragma unroll
    for (int mt = 0; mt < 2; mt++)
#pragma unroll
        for (int nf = 0; nf < 4; nf++)
#pragma unroll
            for (int v = 0; v < 4; v++) {
                int row = mt * 16 + (lane >> 2) + (v >> 1) * 8;
                int col = nf * 8 + (lane & 3) * 2 + (v & 1);
                atomicAdd(&kvbuf[row][col], acc[mt][nf][v]);
            }
    __syncthreads();

    if (tid < 32) {
        float s = 0.f;
#pragma unroll
        for (int i = 0; i < 8; i++) s += ksbuf[i][tid];
        atomicAdd(g_Ksum + nh * HD + tid, s);
    }
    for (int i = tid; i < 1024; i += 256)
        atomicAdd(g_KV + (size_t)nh * 1024 + i, kvbuf[i >> 5][i & 31]);
}

// ---------------- prep kernels (critical path vs side path) ----------------
__device__ __forceinline__ void tohalf4(const float* s, __half* d, size_t si, size_t di) {
    float4 v = *(const float4*)(s + si * 4);
    __half2* dp = (__half2*)(d + di);
    dp[0] = __halves2half2(__float2half_rn(v.x), __float2half_rn(v.y));
    dp[1] = __halves2half2(__float2half_rn(v.z), __float2half_rn(v.w));
}

#define NW4  16384
#define NW1  65536
#define NW2  32768
#define NACT 2097152
#define PREPKV_TOTAL (2*NW4 + NACT)          // Wk, Wv, source
#define PREPW_TOTAL  (NW4 + NW1 + NW2)       // Wq, W1, W2

// critical path: Wk/Wv + source + zero accumulators
__global__ __launch_bounds__(256)
void prep_kv_kernel(const float* __restrict__ Wk, const float* __restrict__ Wv,
                    const float* __restrict__ src)
{
    int i = blockIdx.x * 256 + threadIdx.x;
    if (i < NB * HH * HD * HD) g_KV[i] = 0.f;
    if (i < NB * HH * HD)      g_Ksum[i] = 0.f;
    if (i >= PREPKV_TOTAL) return;

    int r = i;
    if (r < NW4) { tohalf4(Wk, g_wkv, r, (size_t)r * 4); return; }
    r -= NW4;
    if (r < NW4) { tohalf4(Wv, g_wkv, r, (size_t)(65536 + r * 4)); return; }
    r -= NW4;
    tohalf4(src, g_ss_h, r, (size_t)r * 4);
}

// side path: Wq/W1/W2 converts (needed only from the qz GEMM onward)
__global__ __launch_bounds__(256)
void prep_w_kernel(const float* __restrict__ Wq, const float* __restrict__ W1,
                   const float* __restrict__ W2)
{
    int r = blockIdx.x * 256 + threadIdx.x;
    if (r >= PREPW_TOTAL) return;
    if (r < NW4) { tohalf4(Wq, g_wq, r, (size_t)r * 4); return; }
    r -= NW4;
    if (r < NW1) { tohalf4(W1, g_w1, r, (size_t)r * 4); return; }
    r -= NW1;
    tohalf4(W2, g_w2, r, (size_t)r * 4);
}

// side path: x -> cat[:,0:256]
__global__ __launch_bounds__(256)
void prep_b_kernel(const float* __restrict__ x)
{
    int r = blockIdx.x * 256 + threadIdx.x;
    if (r >= NACT) return;
    int e0  = r * 4;
    int row = e0 >> 8;
    int col = e0 & 255;
    tohalf4(x, g_cat_h, r, (size_t)row * D2 + col);
}

// ------ G[n][j][h*32+d] = (1/SS) sum_e KV[n,h,d,e]*Wm[j,h*32+e] ------------
__global__ __launch_bounds__(256)
void g_kernel(const float* __restrict__ Wm)
{
    __shared__ float KVsT[HD][HD + 1];
    const int h = blockIdx.x;
    const int n = blockIdx.y;
    const int z = blockIdx.z;
    const int tid = threadIdx.x;

    for (int i = tid; i < HD * HD; i += 256) {
        int d = i >> 5, e = i & 31;
        KVsT[e][d] = g_KV[((size_t)(n * HH + h)) * HD * HD + i];
    }
    __syncthreads();

    const int d  = tid & 31;
    const int j0 = z * 32 + (tid >> 5) * 4;
    const float inv_ss = 1.f / (float)SS;
#pragma unroll
    for (int i = 0; i < 4; i++) {
        int j = j0 + i;
        const float* wrow = Wm + (size_t)j * DD + h * HD;
        float acc = 0.f;
#pragma unroll
        for (int e = 0; e < HD; e++) acc += KVsT[e][d] * wrow[e];
        ((__half*)g_G)[((size_t)n * DD + j) * DD + h * HD + d] =
            __float2half_rn(acc * inv_ss);
    }
}

// ---------------- host ----------------
static float* sym_f(const void* s) { void* p = nullptr; cudaGetSymbolAddress(&p, s); return (float*)p; }
static __half* sym_h(const void* s) { void* p = nullptr; cudaGetSymbolAddress(&p, s); return (__half*)p; }

extern "C" void kernel_launch(void* const* d_in, const int* in_sizes, int n_in,
                              void* d_out, int out_size)
{
    const float* x           = (const float*)d_in[0];
    const float* source      = (const float*)d_in[1];
    const float* x_mask      = (const float*)d_in[2];
    const float* source_mask = (const float*)d_in[3];
    const float* Wq          = (const float*)d_in[4];
    const float* Wk          = (const float*)d_in[5];
    const float* Wv          = (const float*)d_in[6];
    const float* Wm          = (const float*)d_in[7];
    const float* W1          = (const float*)d_in[8];
    const float* W2          = (const float*)d_in[9];
    const float* g1          = (const float*)d_in[10];
    const float* b1          = (const float*)d_in[11];
    const float* g2          = (const float*)d_in[12];
    const float* b2          = (const float*)d_in[13];
    float* out = (float*)d_out;

    float* pKsum = sym_f(g_Ksum);

    __half *pss = sym_h(g_ss_h), *pqz = sym_h(g_qz_h);
    __half *pct = sym_h(g_cat_h), *ph1 = sym_h(g_h1_h);
    __half *pkvh = sym_h(g_kvh);
    __half *pwq = sym_h(g_wq), *pwkv = sym_h(g_wkv);
    __half *pw1 = sym_h(g_w1), *pw2 = sym_h(g_w2), *pG = sym_h(g_G);

    cudaFuncSetAttribute(gemm128p<ACT_KVMIX, true,  EPI_HALF>, cudaFuncAttributeMaxDynamicSharedMemorySize, GSMEM128);
    cudaFuncSetAttribute(gemm128p<ACT_ELU1,  true,  EPI_QZ  >, cudaFuncAttributeMaxDynamicSharedMemorySize, GSMEM128);
    cudaFuncSetAttribute(gemm128p<ACT_RELU,  false, EPI_HALF>, cudaFuncAttributeMaxDynamicSharedMemorySize, GSMEM128);
    cudaFuncSetAttribute(gemm256p<EPI_LNCAT, true >, cudaFuncAttributeMaxDynamicSharedMemorySize, GSMEM256);
    cudaFuncSetAttribute(gemm256p<EPI_LNRES, false>, cudaFuncAttributeMaxDynamicSharedMemorySize, GSMEM256);

    int nsm = 148;
    cudaDeviceGetAttribute(&nsm, cudaDevAttrMultiProcessorCount, 0);
    const int pgrid = 2 * nsm;

    static cudaStream_t s1 = nullptr;
    static cudaEvent_t evStart, evB, evK, evG;
    if (s1 == nullptr) {
        cudaStreamCreateWithFlags(&s1, cudaStreamNonBlocking);
        cudaEventCreateWithFlags(&evStart, cudaEventDisableTiming);
        cudaEventCreateWithFlags(&evB,     cudaEventDisableTiming);
        cudaEventCreateWithFlags(&evK,     cudaEventDisableTiming);
        cudaEventCreateWithFlags(&evG,     cudaEventDisableTiming);
    }

    dim3 blk(256);

    // fork
    cudaEventRecord(evStart, 0);
    cudaStreamWaitEvent(s1, evStart, 0);

    // s1: x -> cat[:,0:256], then Wq/W1/W2 converts
    prep_b_kernel<<<(NACT + 255) / 256, blk, 0, s1>>>(x);
    prep_w_kernel<<<(PREPW_TOTAL + 255) / 256, blk, 0, s1>>>(Wq, W1, W2);
    cudaEventRecord(evB, s1);

    // s0: Wk/Wv + source converts + zero accumulators (critical path)
    prep_kv_kernel<<<(PREPKV_TOTAL + 255) / 256, blk>>>(Wk, Wv, source);

    // s0: merged K|V projection -> g_kvh (fp16), elu1 on K half only
    gemm128p<ACT_KVMIX, true, EPI_HALF><<<pgrid, blk, GSMEM128>>>(pss, pwkv, DD,
        nullptr, pkvh, D2, DD, source_mask, 1.f, nullptr);

    // s0: KV + Ksum via 2-stage pipelined tensor-core kernel
    kv_tc<<<dim3(NB * HH, 8), blk>>>(pkvh);
    cudaEventRecord(evK, 0);

    // s1: G = (KV@Wm)/SS  (overlaps qz on s0)
    cudaStreamWaitEvent(s1, evK, 0);
    g_kernel<<<dim3(HH, NB, 8), blk, 0, s1>>>(Wm);
    cudaEventRecord(evG, s1);

    // s0: Q projection with fused Z
    cudaStreamWaitEvent(0, evB, 0);
    gemm128p<ACT_ELU1, true, EPI_QZ><<<pgrid, blk, GSMEM128>>>(pct, pwq, D2,
        nullptr, pqz, DD, DD, x_mask, 1.f, pKsum);

    // s0: msg2 = qz @ G[n].T with fused LN(g1,b1) -> cat[:,256:512] (join evG)
    cudaStreamWaitEvent(0, evG, 0);
    gemm256p<EPI_LNCAT, true><<<pgrid, blk, GSMEM256>>>(pqz, pG, DD, DD,
        g1, b1, nullptr, nullptr, pct);

    // s0: h1 = relu(cat @ W1.T)
    gemm128p<ACT_RELU, false, EPI_HALF><<<pgrid, blk, GSMEM128>>>(pct, pw1, D2,
        nullptr, ph1, D2, D2, nullptr, 1.f, nullptr);

    // s0: out = x + LN(h1 @ W2.T)
    gemm256p<EPI_LNRES, false><<<pgrid, blk, GSMEM256>>>(ph1, pw2, D2, D2,
        g2, b2, x, out, nullptr);
}

// round 17
// speedup vs baseline: 1.0631x; 1.0007x over previous
#include <cuda_runtime.h>
#include <cuda_fp16.h>
#include <math.h>
#include <stdint.h>

// ---------------- problem constants ----------------
#define NB   4
#define LQ   8192
#define SS   8192
#define DD   256
#define HH   8
#define HD   32
#define D2   512
#define MR   (NB*LQ)        // 32768
#define EPS_ATTN 1e-6f
#define EPS_LN   1e-5f

// ---------------- scratch (device globals) ----------------
__device__ float g_KV  [NB*HH*HD*HD];
__device__ float g_Ksum[NB*HH*HD];

__device__ __half g_ss_h [(size_t)MR*DD];
__device__ __half g_kvh  [(size_t)MR*D2];   // [row][0:256]=K, [256:512]=V (fp16)
__device__ __half g_qz_h [(size_t)MR*DD];
__device__ __half g_cat_h[(size_t)MR*D2];
__device__ __half g_h1_h [(size_t)MR*D2];

__device__ __half g_wq [DD*DD];
__device__ __half g_wkv[D2*DD];             // rows 0-255 Wk, 256-511 Wv
__device__ __half g_w1 [D2*D2];
__device__ __half g_w2 [DD*D2];
__device__ __half g_G  [NB*DD*DD];          // per-batch effective weight (KV@Wm)/SS

// ---------------- low-level helpers ----------------
__device__ __forceinline__ uint32_t smem_u32(const void* p) {
    uint32_t a;
    asm("{ .reg .u64 t; cvta.to.shared.u64 t, %1; cvt.u32.u64 %0, t; }"
        : "=r"(a) : "l"(p));
    return a;
}

__device__ __forceinline__ uint32_t sw128(uint32_t off) {
    return off ^ ((off >> 3) & 0x70);
}

#define CPASYNC16(sa, ga) \
    asm volatile("cp.async.cg.shared.global [%0], [%1], 16;" \
                 :: "r"(sa), "l"(ga) : "memory")
#define CPCOMMIT() asm volatile("cp.async.commit_group;" ::: "memory")
#define CPWAIT0()  asm volatile("cp.async.wait_group 0;" ::: "memory")
#define CPWAIT1()  asm volatile("cp.async.wait_group 1;" ::: "memory")

#define LDSM4(r, addr) \
    asm volatile("ldmatrix.sync.aligned.m8n8.x4.shared.b16 {%0,%1,%2,%3}, [%4];" \
        : "=r"((r)[0]), "=r"((r)[1]), "=r"((r)[2]), "=r"((r)[3]) : "r"(addr))

#define LDSM4T(r, addr) \
    asm volatile("ldmatrix.sync.aligned.m8n8.x4.trans.shared.b16 {%0,%1,%2,%3}, [%4];" \
        : "=r"((r)[0]), "=r"((r)[1]), "=r"((r)[2]), "=r"((r)[3]) : "r"(addr))

__device__ __forceinline__ void mma_f16(float* c, const uint32_t* a,
                                        uint32_t b0, uint32_t b1) {
    asm volatile(
        "mma.sync.aligned.m16n8k16.row.col.f32.f16.f16.f32 "
        "{%0,%1,%2,%3}, {%4,%5,%6,%7}, {%8,%9}, {%0,%1,%2,%3};"
        : "+f"(c[0]), "+f"(c[1]), "+f"(c[2]), "+f"(c[3])
        : "r"(a[0]), "r"(a[1]), "r"(a[2]), "r"(a[3]), "r"(b0), "r"(b1));
}

enum { ACT_NONE = 0, ACT_ELU1 = 1, ACT_RELU = 2, ACT_KVMIX = 3 };
enum { EPI_F32 = 0, EPI_HALF = 1, EPI_QZ = 2 };
enum { EPI_LNCAT = 0, EPI_LNRES = 1 };

// ====== persistent GEMM, 128x128 tile, 3-stage single-sync pipeline =======
#define T_BYTES   16384u
#define STG128    (2u*T_BYTES)     // 32KB/stage
#define GSMEM128  (3u*STG128)      // 96KB (3 stages)

template<int ACT, bool HASMASK, int EPI>
__global__ __launch_bounds__(256, 2)
void gemm128p(const __half* __restrict__ Ap, const __half* __restrict__ Bp, int lda,
              float* __restrict__ C, __half* __restrict__ Ch,
              int Nc, int K, const float* __restrict__ mask, float scale,
              const float* __restrict__ Ksum)
{
    extern __shared__ char smem[];
    const uint32_t sb = smem_u32(smem);
    const int tid  = threadIdx.x;
    const int lane = tid & 31;
    const int wid  = tid >> 5;
    const int wm   = wid >> 1;
    const int wn   = wid & 1;

    const int Ntl = Nc >> 7;
    const int T   = (MR >> 7) * Ntl;
    const int NCC = K >> 6;

    auto load_chunk = [&](int buf, int bm, int bn, int c) {
        const int k0 = c * 64;
        const uint32_t stb = sb + (uint32_t)buf * STG128;
#pragma unroll
        for (int i = 0; i < 4; i++) {
            int ci  = tid + 256 * i;
            int row = ci >> 3;
            int c16 = ci & 7;
            uint32_t so = sw128((uint32_t)(row * 128 + c16 * 16));
            CPASYNC16(stb + so,           Ap + (size_t)(bm + row) * lda + k0 + c16 * 8);
            CPASYNC16(stb + T_BYTES + so, Bp + (size_t)(bn + row) * K   + k0 + c16 * 8);
        }
        CPCOMMIT();
    };

    const int t0 = blockIdx.x;
    if (t0 >= T) return;

    // cross-tile chunk lookahead
    int lt = t0, lc = 0, gi = 0, k = 0;
    auto issue = [&]() {
        if (lt < T) {
            load_chunk(gi % 3, (lt / Ntl) * 128, (lt % Ntl) * 128, lc);
            gi++;
            if (++lc == NCC) { lc = 0; lt += gridDim.x; }
        }
    };
    issue(); issue();   // prologue: 2 chunks in flight

    const int a_row = wm * 32 + (lane & 15);
    const int a_kb  = (lane >> 4) * 16;
    const int b_row = wn * 64 + (lane & 7) + ((lane >> 4) << 3);
    const int b_kb  = ((lane >> 3) & 1) * 16;

    for (int t = t0; t < T; t += gridDim.x) {
        const int bm = (t / Ntl) * 128;
        const int bn = (t % Ntl) * 128;

        float acc[2][8][4];
#pragma unroll
        for (int i = 0; i < 2; i++)
#pragma unroll
            for (int j = 0; j < 8; j++)
#pragma unroll
                for (int v = 0; v < 4; v++) acc[i][j][v] = 0.f;

        for (int c = 0; c < NCC; c++) {
            if (gi - k > 1) { CPWAIT1(); }    // chunk k is the oldest of >=2
            else            { CPWAIT0(); }    // tail: only chunk k pending
            __syncthreads();                  // publishes chunk k; proves k-1 computed
            issue();                          // overwrite buf computed at k-1 (safe)

            const uint32_t stb = sb + (uint32_t)(k % 3) * STG128;
#pragma unroll
            for (int ks = 0; ks < 4; ks++) {
                uint32_t ah[2][4], bh[4][4];
#pragma unroll
                for (int mt = 0; mt < 2; mt++) {
                    uint32_t ra = sw128((uint32_t)((a_row + mt * 16) * 128 + ks * 32 + a_kb));
                    LDSM4(ah[mt], stb + ra);
                }
#pragma unroll
                for (int ntp = 0; ntp < 4; ntp++) {
                    uint32_t rb = sw128((uint32_t)((b_row + ntp * 16) * 128 + ks * 32 + b_kb));
                    LDSM4(bh[ntp], stb + T_BYTES + rb);
                }
#pragma unroll
                for (int mt = 0; mt < 2; mt++)
#pragma unroll
                    for (int nt = 0; nt < 8; nt++) {
                        const int ntp = nt >> 1, o = (nt & 1) * 2;
                        mma_f16(acc[mt][nt], ah[mt], bh[ntp][o], bh[ntp][o + 1]);
                    }
            }
            k++;
        }

        // ------------- register-direct epilogue -------------
        {
            const bool elu = (ACT == ACT_ELU1) || (ACT == ACT_KVMIX && bn < DD);
            float mk[2][2];
#pragma unroll
            for (int mt = 0; mt < 2; mt++)
#pragma unroll
                for (int rh = 0; rh < 2; rh++) {
                    int m = bm + wm * 32 + mt * 16 + (lane >> 2) + rh * 8;
                    mk[mt][rh] = (HASMASK ? mask[m] : 1.f) * scale;
                }
#pragma unroll
            for (int mt = 0; mt < 2; mt++)
#pragma unroll
                for (int nt = 0; nt < 8; nt++)
#pragma unroll
                    for (int v = 0; v < 4; v++) {
                        float xv = acc[mt][nt][v];
                        if (ACT == ACT_ELU1 || ACT == ACT_KVMIX) {
                            if (elu) xv = (xv > 0.f) ? (xv + 1.f) : expf(xv);
                        } else if (ACT == ACT_RELU) xv = fmaxf(xv, 0.f);
                        acc[mt][nt][v] = xv * mk[mt][v >> 1];
                    }

            if (EPI == EPI_QZ) {
                const int n = bm / LQ;
                float ksv[8][2];
#pragma unroll
                for (int nt = 0; nt < 8; nt++)
#pragma unroll
                    for (int j = 0; j < 2; j++)
                        ksv[nt][j] = Ksum[n * DD + bn + wn * 64 + nt * 8 + (lane & 3) * 2 + j];

                float p[2][2][2];
#pragma unroll
                for (int mt = 0; mt < 2; mt++)
#pragma unroll
                    for (int rh = 0; rh < 2; rh++)
#pragma unroll
                        for (int hg = 0; hg < 2; hg++) p[mt][rh][hg] = 0.f;
#pragma unroll
                for (int mt = 0; mt < 2; mt++)
#pragma unroll
                    for (int nt = 0; nt < 8; nt++)
#pragma unroll
                        for (int v = 0; v < 4; v++)
                            p[mt][v >> 1][nt >> 2] += acc[mt][nt][v] * ksv[nt][v & 1];

                float z[2][2][2];
#pragma unroll
                for (int mt = 0; mt < 2; mt++)
#pragma unroll
                    for (int rh = 0; rh < 2; rh++)
#pragma unroll
                        for (int hg = 0; hg < 2; hg++) {
                            float s = p[mt][rh][hg];
                            s += __shfl_xor_sync(0xffffffffu, s, 1);
                            s += __shfl_xor_sync(0xffffffffu, s, 2);
                            // SS keeps qz in fp16-normal range; 1/SS folded into G.
                            z[mt][rh][hg] = (float)SS / (s + EPS_ATTN);
                        }

#pragma unroll
                for (int mt = 0; mt < 2; mt++)
#pragma unroll
                    for (int nt = 0; nt < 8; nt++)
#pragma unroll
                        for (int rh = 0; rh < 2; rh++) {
                            int row = bm + wm * 32 + mt * 16 + (lane >> 2) + rh * 8;
                            int col = bn + wn * 64 + nt * 8 + (lane & 3) * 2;
                            float zz = z[mt][rh][nt >> 2];
                            float v0 = acc[mt][nt][rh * 2]     * zz;
                            float v1 = acc[mt][nt][rh * 2 + 1] * zz;
                            *(__half2*)(Ch + (size_t)row * DD + col) =
                                __halves2half2(__float2half_rn(v0), __float2half_rn(v1));
                        }
            } else {
#pragma unroll
                for (int mt = 0; mt < 2; mt++)
#pragma unroll
                    for (int nt = 0; nt < 8; nt++)
#pragma unroll
                        for (int rh = 0; rh < 2; rh++) {
                            int row = bm + wm * 32 + mt * 16 + (lane >> 2) + rh * 8;
                            int col = bn + wn * 64 + nt * 8 + (lane & 3) * 2;
                            float v0 = acc[mt][nt][rh * 2];
                            float v1 = acc[mt][nt][rh * 2 + 1];
                            size_t gi2 = (size_t)row * Nc + col;
                            if (EPI == EPI_HALF) {
                                *(__half2*)(Ch + gi2) =
                                    __halves2half2(__float2half_rn(v0), __float2half_rn(v1));
                            } else {
                                *(float2*)(C + gi2) = make_float2(v0, v1);
                            }
                        }
            }
        }
    }
}

// ===== persistent GEMM 64x256 tile, single-sync, fused row-LN epilogue =====
#define A_SZ   8192u
#define B_SZ   32768u
#define STG256 (A_SZ + B_SZ)            // 40KB
#define SUMS_OFF (2u*STG256)            // 80KB
#define GSMEM256 (SUMS_OFF + 2048u)     // +2KB for row sums

template<int EPI, bool BATCHB>
__global__ __launch_bounds__(256, 2)
void gemm256p(const __half* __restrict__ Ap, const __half* __restrict__ Bp,
              int lda, int K,
              const float* __restrict__ gv_, const float* __restrict__ bv_,
              const float* __restrict__ xres,
              float* __restrict__ outf, __half* __restrict__ Ch)
{
    extern __shared__ char smem[];
    const uint32_t sb = smem_u32(smem);
    float* sums  = (float*)(smem + SUMS_OFF);   // [64][4]
    float* sumsq = sums + 256;                  // [64][4]
    const int tid  = threadIdx.x;
    const int lane = tid & 31;
    const int wid  = tid >> 5;
    const int wm   = wid >> 2;
    const int wn   = wid & 3;

    const int T   = MR / 64;   // 512
    const int NCC = K >> 6;

    float gvr[8][2], bvr[8][2];
#pragma unroll
    for (int nt = 0; nt < 8; nt++)
#pragma unroll
        for (int j = 0; j < 2; j++) {
            int col = wn * 64 + nt * 8 + (lane & 3) * 2 + j;
            gvr[nt][j] = gv_[col];
            bvr[nt][j] = bv_[col];
        }

    auto load_chunk = [&](int buf, int bm, int c) {
        const int k0 = c * 64;
        const uint32_t stb = sb + (uint32_t)buf * STG256;
        const __half* Bt = BATCHB ? Bp + (size_t)(bm / LQ) * DD * DD : Bp;
#pragma unroll
        for (int i = 0; i < 10; i++) {
            int ci = tid + 256 * i;
            if (i < 2) {
                int row = ci >> 3, c16 = ci & 7;
                uint32_t so = sw128((uint32_t)(row * 128 + c16 * 16));
                CPASYNC16(stb + so, Ap + (size_t)(bm + row) * lda + k0 + c16 * 8);
            } else {
                int idx = ci - 512;
                int row = idx >> 3, c16 = idx & 7;
                uint32_t so = sw128((uint32_t)(row * 128 + c16 * 16));
                CPASYNC16(stb + A_SZ + so, Bt + (size_t)row * K + k0 + c16 * 8);
            }
        }
        CPCOMMIT();
    };

    const int t0 = blockIdx.x;
    if (t0 >= T) return;

    int lt = t0, lc = 0, gi = 0, k = 0;
    auto issue = [&]() {
        if (lt < T) {
            load_chunk(gi & 1, lt * 64, lc);
            gi++;
            if (++lc == NCC) { lc = 0; lt += gridDim.x; }
        }
    };
    issue();   // prologue: 1 chunk in flight

    const int a_row = wm * 32 + (lane & 15);
    const int a_kb  = (lane >> 4) * 16;
    const int b_row = wn * 64 + (lane & 7) + ((lane >> 4) << 3);
    const int b_kb  = ((lane >> 3) & 1) * 16;

    for (int t = t0; t < T; t += gridDim.x) {
        const int bm = t * 64;

        float acc[2][8][4];
#pragma unroll
        for (int i = 0; i < 2; i++)
#pragma unroll
            for (int j = 0; j < 8; j++)
#pragma unroll
                for (int v = 0; v < 4; v++) acc[i][j][v] = 0.f;

        for (int c = 0; c < NCC; c++) {
            CPWAIT0();
            __syncthreads();
            issue();

            const uint32_t stb = sb + (uint32_t)(k & 1) * STG256;
#pragma unroll
            for (int ks = 0; ks < 4; ks++) {
                uint32_t ah[2][4], bh[4][4];
#pragma unroll
                for (int mt = 0; mt < 2; mt++) {
                    uint32_t ra = sw128((uint32_t)((a_row + mt * 16) * 128 + ks * 32 + a_kb));
                    LDSM4(ah[mt], stb + ra);
                }
#pragma unroll
                for (int ntp = 0; ntp < 4; ntp++) {
                    uint32_t rb = sw128((uint32_t)((b_row + ntp * 16) * 128 + ks * 32 + b_kb));
                    LDSM4(bh[ntp], stb + A_SZ + rb);
                }
#pragma unroll
                for (int mt = 0; mt < 2; mt++)
#pragma unroll
                    for (int nt = 0; nt < 8; nt++) {
                        const int ntp = nt >> 1, o = (nt & 1) * 2;
                        mma_f16(acc[mt][nt], ah[mt], bh[ntp][o], bh[ntp][o + 1]);
                    }
            }
            k++;
        }

        // ------- LN epilogue: quad-shfl partial sums + 2KB smem reduce -------
#pragma unroll
        for (int mt = 0; mt < 2; mt++)
#pragma unroll
            for (int rh = 0; rh < 2; rh++) {
                float s = 0.f, s2 = 0.f;
#pragma unroll
                for (int nt = 0; nt < 8; nt++) {
                    float v0 = acc[mt][nt][rh * 2], v1 = acc[mt][nt][rh * 2 + 1];
                    s  += v0 + v1;
                    s2 += v0 * v0 + v1 * v1;
                }
                s  += __shfl_xor_sync(0xffffffffu, s, 1);
                s  += __shfl_xor_sync(0xffffffffu, s, 2);
                s2 += __shfl_xor_sync(0xffffffffu, s2, 1);
                s2 += __shfl_xor_sync(0xffffffffu, s2, 2);
                int rloc = wm * 32 + mt * 16 + (lane >> 2) + rh * 8;
                if ((lane & 3) == 0) {
                    sums [rloc * 4 + wn] = s;
                    sumsq[rloc * 4 + wn] = s2;
                }
            }
        __syncthreads();

#pragma unroll
        for (int mt = 0; mt < 2; mt++)
#pragma unroll
            for (int rh = 0; rh < 2; rh++) {
                int rloc = wm * 32 + mt * 16 + (lane >> 2) + rh * 8;
                float st = 0.f, s2t = 0.f;
#pragma unroll
                for (int k2 = 0; k2 < 4; k2++) {
                    st  += sums [rloc * 4 + k2];
                    s2t += sumsq[rloc * 4 + k2];
                }
                const float mu  = st * (1.f / 256.f);
                const float var = s2t * (1.f / 256.f) - mu * mu;
                const float rs  = rsqrtf(var + EPS_LN);
                const size_t gr = (size_t)(bm + rloc);
#pragma unroll
                for (int nt = 0; nt < 8; nt++) {
                    int col = wn * 64 + nt * 8 + (lane & 3) * 2;
                    float y0 = (acc[mt][nt][rh * 2]     - mu) * rs * gvr[nt][0] + bvr[nt][0];
                    float y1 = (acc[mt][nt][rh * 2 + 1] - mu) * rs * gvr[nt][1] + bvr[nt][1];
                    if (EPI == EPI_LNCAT) {
                        *(__half2*)(Ch + gr * D2 + DD + col) =
                            __halves2half2(__float2half_rn(y0), __float2half_rn(y1));
                    } else {
                        float2 xr = *(const float2*)(xres + gr * DD + col);
                        *(float2*)(outf + gr * DD + col) =
                            make_float2(xr.x + y0, xr.y + y1);
                    }
                }
            }
        __syncthreads();
    }
}

// ====== KV via tensor cores: 2-stage pipeline (R13-calibrated optimum) =====
__global__ __launch_bounds__(256, 2)
void kv_tc(const __half* __restrict__ KVh)
{
    __shared__ __half Ks[2][128][40];
    __shared__ __half Vs[2][128][40];
    __shared__ float kvbuf[32][33];
    __shared__ float ksbuf[8][32];

    const int nh = blockIdx.x;
    const int n  = nh >> 3;
    const int h  = nh & 7;
    const int sbase = blockIdx.y * 1024;
    const int tid = threadIdx.x, lane = tid & 31, w = tid >> 5;

    const uint32_t ksb = smem_u32(&Ks[0][0][0]);
    const uint32_t vsb = smem_u32(&Vs[0][0][0]);

    auto load = [&](int st, int ch) {
        const int s0 = sbase + ch * 128;
        const uint32_t ko = ksb + st * 10240u;
        const uint32_t vo = vsb + st * 10240u;
#pragma unroll
        for (int i = 0; i < 2; i++) {
            int idx = tid + 256 * i;
            int row = idx >> 2, c = idx & 3;
            size_t gk = (size_t)(n * SS + s0 + row) * D2 + h * HD + c * 8;
            CPASYNC16(ko + (uint32_t)(row * 80 + c * 16), KVh + gk);
            CPASYNC16(vo + (uint32_t)(row * 80 + c * 16), KVh + gk + DD);
        }
        CPCOMMIT();
    };

    for (int i = tid; i < 32 * 33; i += 256) (&kvbuf[0][0])[i] = 0.f;

    float acc[2][4][4];
#pragma unroll
    for (int mt = 0; mt < 2; mt++)
#pragma unroll
        for (int nf = 0; nf < 4; nf++)
#pragma unroll
            for (int v = 0; v < 4; v++) acc[mt][nf][v] = 0.f;
    float ksacc = 0.f;

    load(0, 0);

    const int q = lane >> 3, r = lane & 7;
    const int kr = w * 16;
    const int ksd = tid & 31, ksr = tid >> 5;

    for (int ch = 0; ch < 8; ch++) {
        if (ch + 1 < 8) { load((ch + 1) & 1, ch + 1); CPWAIT1(); }
        else            { CPWAIT0(); }
        __syncthreads();

        const int st = ch & 1;
        const uint32_t ko = ksb + (uint32_t)(st * 10240);
        const uint32_t vo = vsb + (uint32_t)(st * 10240);

#pragma unroll
        for (int i = 0; i < 16; i++)
            ksacc += __half2float(Ks[st][ksr + 8 * i][ksd]);

        uint32_t a[2][4], bx[4], by[4];
#pragma unroll
        for (int mt = 0; mt < 2; mt++) {
            uint32_t addr = ko + (uint32_t)((kr + (q >> 1) * 8 + r) * 80
                                            + ((q & 1) * 8 + mt * 16) * 2);
            LDSM4T(a[mt], addr);
        }
        {
            uint32_t rowb = (uint32_t)((kr + (q & 1) * 8 + r) * 80);
            LDSM4T(bx, vo + rowb + (uint32_t)(((q >> 1) * 8) * 2));
            LDSM4T(by, vo + rowb + (uint32_t)(((q >> 1) * 8 + 16) * 2));
        }
#pragma unroll
        for (int mt = 0; mt < 2; mt++) {
            mma_f16(acc[mt][0], a[mt], bx[0], bx[1]);
            mma_f16(acc[mt][1], a[mt], bx[2], bx[3]);
            mma_f16(acc[mt][2], a[mt], by[0], by[1]);
            mma_f16(acc[mt][3], a[mt], by[2], by[3]);
        }
        __syncthreads();
    }

    ksbuf[ksr][ksd] = ksacc;
    __syncthreads();

#pragma unroll
    for (int mt = 0; mt < 2; mt++)
#pragma unroll
        for (int nf = 0; nf < 4; nf++)
#pragma unroll
            for (int v = 0; v < 4; v++) {
                int row = mt * 16 + (lane >> 2) + (v >> 1) * 8;
                int col = nf * 8 + (lane & 3) * 2 + (v & 1);
                atomicAdd(&kvbuf[row][col], acc[mt][nf][v]);
            }
    __syncthreads();

    if (tid < 32) {
        float s = 0.f;
#pragma unroll
        for (int i = 0; i < 8; i++) s += ksbuf[i][tid];
        atomicAdd(g_Ksum + nh * HD + tid, s);
    }
    for (int i = tid; i < 1024; i += 256)
        atomicAdd(g_KV + (size_t)nh * 1024 + i, kvbuf[i >> 5][i & 31]);
}

// ---------------- prep kernels (critical path vs side path) ----------------
__device__ __forceinline__ void tohalf4(const float* s, __half* d, size_t si, size_t di) {
    float4 v = *(const float4*)(s + si * 4);
    __half2* dp = (__half2*)(d + di);
    dp[0] = __halves2half2(__float2half_rn(v.x), __float2half_rn(v.y));
    dp[1] = __halves2half2(__float2half_rn(v.z), __float2half_rn(v.w));
}

#define NW4  16384
#define NW1  65536
#define NW2  32768
#define NACT 2097152
#define PREPKV_TOTAL (2*NW4 + NACT)          // Wk, Wv, source
#define PREPW_TOTAL  (NW4 + NW1 + NW2)       // Wq, W1, W2

__global__ __launch_bounds__(256)
void prep_kv_kernel(const float* __restrict__ Wk, const float* __restrict__ Wv,
                    const float* __restrict__ src)
{
    int i = blockIdx.x * 256 + threadIdx.x;
    if (i < NB * HH * HD * HD) g_KV[i] = 0.f;
    if (i < NB * HH * HD)      g_Ksum[i] = 0.f;
    if (i >= PREPKV_TOTAL) return;

    int r = i;
    if (r < NW4) { tohalf4(Wk, g_wkv, r, (size_t)r * 4); return; }
    r -= NW4;
    if (r < NW4) { tohalf4(Wv, g_wkv, r, (size_t)(65536 + r * 4)); return; }
    r -= NW4;
    tohalf4(src, g_ss_h, r, (size_t)r * 4);
}

__global__ __launch_bounds__(256)
void prep_w_kernel(const float* __restrict__ Wq, const float* __restrict__ W1,
                   const float* __restrict__ W2)
{
    int r = blockIdx.x * 256 + threadIdx.x;
    if (r >= PREPW_TOTAL) return;
    if (r < NW4) { tohalf4(Wq, g_wq, r, (size_t)r * 4); return; }
    r -= NW4;
    if (r < NW1) { tohalf4(W1, g_w1, r, (size_t)r * 4); return; }
    r -= NW1;
    tohalf4(W2, g_w2, r, (size_t)r * 4);
}

__global__ __launch_bounds__(256)
void prep_b_kernel(const float* __restrict__ x)
{
    int r = blockIdx.x * 256 + threadIdx.x;
    if (r >= NACT) return;
    int e0  = r * 4;
    int row = e0 >> 8;
    int col = e0 & 255;
    tohalf4(x, g_cat_h, r, (size_t)row * D2 + col);
}

// ------ G[n][j][h*32+d] = (1/SS) sum_e KV[n,h,d,e]*Wm[j,h*32+e] ------------
__global__ __launch_bounds__(256)
void g_kernel(const float* __restrict__ Wm)
{
    __shared__ float KVsT[HD][HD + 1];
    const int h = blockIdx.x;
    const int n = blockIdx.y;
    const int z = blockIdx.z;
    const int tid = threadIdx.x;

    for (int i = tid; i < HD * HD; i += 256) {
        int d = i >> 5, e = i & 31;
        KVsT[e][d] = g_KV[((size_t)(n * HH + h)) * HD * HD + i];
    }
    __syncthreads();

    const int d  = tid & 31;
    const int j0 = z * 32 + (tid >> 5) * 4;
    const float inv_ss = 1.f / (float)SS;
#pragma unroll
    for (int i = 0; i < 4; i++) {
        int j = j0 + i;
        const float* wrow = Wm + (size_t)j * DD + h * HD;
        float acc = 0.f;
#pragma unroll
        for (int e = 0; e < HD; e++) acc += KVsT[e][d] * wrow[e];
        ((__half*)g_G)[((size_t)n * DD + j) * DD + h * HD + d] =
            __float2half_rn(acc * inv_ss);
    }
}

// ---------------- host ----------------
static float* sym_f(const void* s) { void* p = nullptr; cudaGetSymbolAddress(&p, s); return (float*)p; }
static __half* sym_h(const void* s) { void* p = nullptr; cudaGetSymbolAddress(&p, s); return (__half*)p; }

extern "C" void kernel_launch(void* const* d_in, const int* in_sizes, int n_in,
                              void* d_out, int out_size)
{
    const float* x           = (const float*)d_in[0];
    const float* source      = (const float*)d_in[1];
    const float* x_mask      = (const float*)d_in[2];
    const float* source_mask = (const float*)d_in[3];
    const float* Wq          = (const float*)d_in[4];
    const float* Wk          = (const float*)d_in[5];
    const float* Wv          = (const float*)d_in[6];
    const float* Wm          = (const float*)d_in[7];
    const float* W1          = (const float*)d_in[8];
    const float* W2          = (const float*)d_in[9];
    const float* g1          = (const float*)d_in[10];
    const float* b1          = (const float*)d_in[11];
    const float* g2          = (const float*)d_in[12];
    const float* b2          = (const float*)d_in[13];
    float* out = (float*)d_out;

    float* pKsum = sym_f(g_Ksum);

    __half *pss = sym_h(g_ss_h), *pqz = sym_h(g_qz_h);
    __half *pct = sym_h(g_cat_h), *ph1 = sym_h(g_h1_h);
    __half *pkvh = sym_h(g_kvh);
    __half *pwq = sym_h(g_wq), *pwkv = sym_h(g_wkv);
    __half *pw1 = sym_h(g_w1), *pw2 = sym_h(g_w2), *pG = sym_h(g_G);

    cudaFuncSetAttribute(gemm128p<ACT_KVMIX, true,  EPI_HALF>, cudaFuncAttributeMaxDynamicSharedMemorySize, GSMEM128);
    cudaFuncSetAttribute(gemm128p<ACT_ELU1,  true,  EPI_QZ  >, cudaFuncAttributeMaxDynamicSharedMemorySize, GSMEM128);
    cudaFuncSetAttribute(gemm128p<ACT_RELU,  false, EPI_HALF>, cudaFuncAttributeMaxDynamicSharedMemorySize, GSMEM128);
    cudaFuncSetAttribute(gemm256p<EPI_LNCAT, true >, cudaFuncAttributeMaxDynamicSharedMemorySize, GSMEM256);
    cudaFuncSetAttribute(gemm256p<EPI_LNRES, false>, cudaFuncAttributeMaxDynamicSharedMemorySize, GSMEM256);

    int nsm = 148;
    cudaDeviceGetAttribute(&nsm, cudaDevAttrMultiProcessorCount, 0);
    const int pgrid = 2 * nsm;

    static cudaStream_t s1 = nullptr;
    static cudaEvent_t evStart, evB, evK, evG;
    if (s1 == nullptr) {
        cudaStreamCreateWithFlags(&s1, cudaStreamNonBlocking);
        cudaEventCreateWithFlags(&evStart, cudaEventDisableTiming);
        cudaEventCreateWithFlags(&evB,     cudaEventDisableTiming);
        cudaEventCreateWithFlags(&evK,     cudaEventDisableTiming);
        cudaEventCreateWithFlags(&evG,     cudaEventDisableTiming);
    }

    dim3 blk(256);

    // fork
    cudaEventRecord(evStart, 0);
    cudaStreamWaitEvent(s1, evStart, 0);

    // s1: x -> cat[:,0:256], then Wq/W1/W2 converts
    prep_b_kernel<<<(NACT + 255) / 256, blk, 0, s1>>>(x);
    prep_w_kernel<<<(PREPW_TOTAL + 255) / 256, blk, 0, s1>>>(Wq, W1, W2);
    cudaEventRecord(evB, s1);

    // s0: Wk/Wv + source converts + zero accumulators (critical path)
    prep_kv_kernel<<<(PREPKV_TOTAL + 255) / 256, blk>>>(Wk, Wv, source);

    // s0: merged K|V projection -> g_kvh (fp16), elu1 on K half only
    gemm128p<ACT_KVMIX, true, EPI_HALF><<<pgrid, blk, GSMEM128>>>(pss, pwkv, DD,
        nullptr, pkvh, D2, DD, source_mask, 1.f, nullptr);

    // s0: KV + Ksum via 2-stage pipelined tensor-core kernel
    kv_tc<<<dim3(NB * HH, 8), blk>>>(pkvh);
    cudaEventRecord(evK, 0);

    // s1: G = (KV@Wm)/SS  (overlaps qz on s0)
    cudaStreamWaitEvent(s1, evK, 0);
    g_kernel<<<dim3(HH, NB, 8), blk, 0, s1>>>(Wm);
    cudaEventRecord(evG, s1);

    // s0: Q projection with fused Z
    cudaStreamWaitEvent(0, evB, 0);
    gemm128p<ACT_ELU1, true, EPI_QZ><<<pgrid, blk, GSMEM128>>>(pct, pwq, D2,
        nullptr, pqz, DD, DD, x_mask, 1.f, pKsum);

    // s0: msg2 = qz @ G[n].T with fused LN(g1,b1) -> cat[:,256:512] (join evG)
    cudaStreamWaitEvent(0, evG, 0);
    gemm256p<EPI_LNCAT, true><<<pgrid, blk, GSMEM256>>>(pqz, pG, DD, DD,
        g1, b1, nullptr, nullptr, pct);

    // s0: h1 = relu(cat @ W1.T)
    gemm128p<ACT_RELU, false, EPI_HALF><<<pgrid, blk, GSMEM128>>>(pct, pw1, D2,
        nullptr, ph1, D2, D2, nullptr, 1.f, nullptr);

    // s0: out = x + LN(h1 @ W2.T)
    gemm256p<EPI_LNRES, false><<<pgrid, blk, GSMEM256>>>(ph1, pw2, D2, D2,
        g2, b2, x, out, nullptr);
}